// round 1
// baseline (speedup 1.0000x reference)
#include <cuda_runtime.h>
#include <math.h>

// Problem dims (fixed per reference setup_inputs)
#define BB   32
#define NNODE 512
#define LL   12
#define HH   64
#define BD   768            // L*H
#define ROWS (BB*NNODE)     // 16384
#define OUTC 64
#define KSUP 4              // order * support_len
#define MDIM 256            // H*K

// ---------------- scratch (device globals; no allocation) ----------------
__device__ float g_res[(size_t)KSUP * ROWS * BD];   // 4 diffusion outputs
__device__ float g_wt[KSUP * BD * OUTC];            // repacked weight [k][d][o]
__device__ float g_mid[(size_t)ROWS * OUTC];        // pre-BN activations
__device__ float g_sum[OUTC];
__device__ float g_sumsq[OUTC];

// ---------------- kernel 0: repack weight [L][M][O] -> Wt[k][d][o] -------
// m = h*4 + k ; d = l*64 + h
__global__ void repack_weight(const float* __restrict__ w) {
    int idx = blockIdx.x * blockDim.x + threadIdx.x;
    const int total = KSUP * BD * OUTC;
    if (idx >= total) return;
    int o = idx % OUTC;
    int d = (idx / OUTC) % BD;
    int k = idx / (OUTC * BD);
    int l = d / HH, h = d % HH;
    g_wt[idx] = w[((size_t)l * MDIM + (size_t)h * KSUP + k) * OUTC + o];
}

// ---------------- kernel 1: diffusion hop  C = (1+eps)*X + A @ X ---------
// Per batch b: A [512,512], X [512,768]. Tiled 128x128x8 SGEMM, 256 thr, 8x8 micro.
__global__ __launch_bounds__(256) void diffusion(
    const float* __restrict__ A,     // [512][512]
    const float* __restrict__ x_in,  // original x (used when in_k < 0)
    int in_k, int out_k,
    const float* __restrict__ eps)
{
    __shared__ float As[8][128];
    __shared__ float Bs[8][128];

    const int b = blockIdx.z;
    const float* Xb = (in_k < 0 ? x_in : g_res + (size_t)in_k * ROWS * BD)
                      + (size_t)b * NNODE * BD;
    float* Cb = g_res + (size_t)out_k * ROWS * BD + (size_t)b * NNODE * BD;

    const int n0 = blockIdx.y * 128;
    const int d0 = blockIdx.x * 128;
    const int tid = threadIdx.x;
    const int tr = tid >> 4;      // 0..15
    const int tc = tid & 15;      // 0..15

    float acc[8][8];
#pragma unroll
    for (int i = 0; i < 8; ++i)
#pragma unroll
        for (int j = 0; j < 8; ++j) acc[i][j] = 0.f;

    for (int k0 = 0; k0 < NNODE; k0 += 8) {
        // load A tile (transposed into As[j][i])
#pragma unroll
        for (int t = 0; t < 4; ++t) {
            int idx = tid + t * 256;
            int i = idx >> 3, j = idx & 7;
            As[j][i] = A[(size_t)(n0 + i) * NNODE + k0 + j];
        }
        // load X tile (row-major, coalesced)
#pragma unroll
        for (int t = 0; t < 4; ++t) {
            int idx = tid + t * 256;
            int j = idx >> 7, i = idx & 127;
            Bs[j][i] = Xb[(size_t)(k0 + j) * BD + d0 + i];
        }
        __syncthreads();

#pragma unroll
        for (int j = 0; j < 8; ++j) {
            float4 a0 = *(const float4*)&As[j][tr * 8];
            float4 a1 = *(const float4*)&As[j][tr * 8 + 4];
            float4 b0 = *(const float4*)&Bs[j][tc * 8];
            float4 b1 = *(const float4*)&Bs[j][tc * 8 + 4];
            float av[8] = {a0.x, a0.y, a0.z, a0.w, a1.x, a1.y, a1.z, a1.w};
            float bv[8] = {b0.x, b0.y, b0.z, b0.w, b1.x, b1.y, b1.z, b1.w};
#pragma unroll
            for (int m = 0; m < 8; ++m)
#pragma unroll
                for (int n = 0; n < 8; ++n)
                    acc[m][n] += av[m] * bv[n];
        }
        __syncthreads();
    }

    const float e1 = 1.0f + eps[0];
#pragma unroll
    for (int m = 0; m < 8; ++m) {
        int row = n0 + tr * 8 + m;
#pragma unroll
        for (int n = 0; n < 8; n += 4) {
            int col = d0 + tc * 8 + n;
            float4 xin = *(const float4*)&Xb[(size_t)row * BD + col];
            float4 v;
            v.x = acc[m][n + 0] + e1 * xin.x;
            v.y = acc[m][n + 1] + e1 * xin.y;
            v.z = acc[m][n + 2] + e1 * xin.z;
            v.w = acc[m][n + 3] + e1 * xin.w;
            *(float4*)&Cb[(size_t)row * BD + col] = v;
        }
    }
}

// ---------------- kernel 2: feature GEMM  mid[r,o] = sum_k sum_d res_k[r,d]*Wt[k,d,o]
// 64x64 tile over rows x OUT, BK=16, 256 threads, 4x4 micro.
__global__ __launch_bounds__(256) void wgemm() {
    __shared__ float As[16][64];
    __shared__ float Bs[16][64];

    const int r0 = blockIdx.x * 64;
    const int tid = threadIdx.x;
    const int tr = tid >> 4;   // 0..15
    const int tc = tid & 15;   // 0..15

    float acc[4][4];
#pragma unroll
    for (int i = 0; i < 4; ++i)
#pragma unroll
        for (int j = 0; j < 4; ++j) acc[i][j] = 0.f;

    for (int kk = 0; kk < KSUP; ++kk) {
        const float* Rk = g_res + (size_t)kk * ROWS * BD;
        const float* Wk = g_wt + (size_t)kk * BD * OUTC;
        for (int d0 = 0; d0 < BD; d0 += 16) {
#pragma unroll
            for (int t = 0; t < 4; ++t) {
                int idx = tid + t * 256;
                int i = idx >> 4, j = idx & 15;
                As[j][i] = Rk[(size_t)(r0 + i) * BD + d0 + j];
            }
#pragma unroll
            for (int t = 0; t < 4; ++t) {
                int idx = tid + t * 256;
                int j = idx >> 6, i = idx & 63;
                Bs[j][i] = Wk[(size_t)(d0 + j) * OUTC + i];
            }
            __syncthreads();
#pragma unroll
            for (int j = 0; j < 16; ++j) {
                float a[4], bv[4];
#pragma unroll
                for (int m = 0; m < 4; ++m) a[m] = As[j][tr * 4 + m];
#pragma unroll
                for (int n = 0; n < 4; ++n) bv[n] = Bs[j][tc * 4 + n];
#pragma unroll
                for (int m = 0; m < 4; ++m)
#pragma unroll
                    for (int n = 0; n < 4; ++n)
                        acc[m][n] += a[m] * bv[n];
            }
            __syncthreads();
        }
    }

#pragma unroll
    for (int m = 0; m < 4; ++m) {
        int row = r0 + tr * 4 + m;
#pragma unroll
        for (int n = 0; n < 4; ++n)
            g_mid[(size_t)row * OUTC + tc * 4 + n] = acc[m][n];
    }
}

// ---------------- kernel 3: zero BN accumulators (deterministic per launch)
__global__ void zero_stats() {
    if (threadIdx.x < OUTC) {
        g_sum[threadIdx.x] = 0.f;
        g_sumsq[threadIdx.x] = 0.f;
    }
}

// ---------------- kernel 4: BN statistics (sum, sumsq per channel) --------
__global__ __launch_bounds__(256) void bn_stats() {
    const int c = threadIdx.x & 63;
    const int rl = threadIdx.x >> 6;    // 0..3
    float s = 0.f, s2 = 0.f;
    for (int r = blockIdx.x * 4 + rl; r < ROWS; r += gridDim.x * 4) {
        float v = g_mid[(size_t)r * OUTC + c];
        s += v;
        s2 += v * v;
    }
    __shared__ float sh[256], sh2[256];
    sh[threadIdx.x] = s;
    sh2[threadIdx.x] = s2;
    __syncthreads();
    if (rl == 0) {
        s  = sh[c]  + sh[c + 64]  + sh[c + 128]  + sh[c + 192];
        s2 = sh2[c] + sh2[c + 64] + sh2[c + 128] + sh2[c + 192];
        atomicAdd(&g_sum[c], s);
        atomicAdd(&g_sumsq[c], s2);
    }
}

// ---------------- kernel 5: BN apply + ReLU + final 64x64 FC --------------
__global__ __launch_bounds__(256) void bn_relu_fc(
    const float* __restrict__ gamma, const float* __restrict__ beta,
    const float* __restrict__ w2,    const float* __restrict__ b2,
    float* __restrict__ out)
{
    __shared__ float w2t[64][65];    // w2t[c][o] = w2[o][c] (padded, conflict-free)
    __shared__ float scale_s[64], shift_s[64];
    __shared__ float y[4][64];

    const int tid = threadIdx.x;
#pragma unroll
    for (int t = 0; t < 16; ++t) {
        int idx = tid + t * 256;
        int o = idx >> 6, c = idx & 63;
        w2t[c][o] = w2[idx];
    }
    if (tid < OUTC) {
        const float invN = 1.0f / (float)ROWS;
        float mean = g_sum[tid] * invN;
        float var  = g_sumsq[tid] * invN - mean * mean;
        float sc   = gamma[tid] * rsqrtf(var + 1e-5f);
        scale_s[tid] = sc;
        shift_s[tid] = beta[tid] - mean * sc;
    }
    __syncthreads();

    const int rl = tid >> 6;     // row lane 0..3
    const int c  = tid & 63;     // channel (and output index)
    for (int r0 = blockIdx.x * 4; r0 < ROWS; r0 += gridDim.x * 4) {
        int r = r0 + rl;
        float v = g_mid[(size_t)r * OUTC + c];
        v = fmaxf(fmaf(v, scale_s[c], shift_s[c]), 0.f);
        y[rl][c] = v;
        __syncthreads();
        float acc = b2[c];
#pragma unroll
        for (int cc = 0; cc < 64; ++cc)
            acc = fmaf(y[rl][cc], w2t[cc][c], acc);
        out[(size_t)r * OUTC + c] = acc;
        __syncthreads();
    }
}

// ---------------- launch ---------------------------------------------------
extern "C" void kernel_launch(void* const* d_in, const int* in_sizes, int n_in,
                              void* d_out, int out_size) {
    const float* x       = (const float*)d_in[0];   // [32,512,12,64]
    const float* support = (const float*)d_in[1];   // [2,512,512]
    const float* weight  = (const float*)d_in[2];   // [12,256,64]
    const float* eps     = (const float*)d_in[3];   // [1]
    const float* gamma   = (const float*)d_in[4];   // [64]
    const float* beta    = (const float*)d_in[5];   // [64]
    const float* w2      = (const float*)d_in[6];   // [64,64]
    const float* b2      = (const float*)d_in[7];   // [64]
    float* out           = (float*)d_out;           // [32,512,64]

    const float* A0 = support;
    const float* A1 = support + (size_t)NNODE * NNODE;

    // repack weight
    {
        int total = KSUP * BD * OUTC;
        repack_weight<<<(total + 255) / 256, 256>>>(weight);
    }

    // diffusion hops; k order = [s0 hop1, s0 hop2, s1 hop1, s1 hop2]
    dim3 grid(BD / 128, NNODE / 128, BB);   // (6,4,32)
    diffusion<<<grid, 256>>>(A0, x, -1, 0, eps);
    diffusion<<<grid, 256>>>(A0, x,  0, 1, eps);
    diffusion<<<grid, 256>>>(A1, x, -1, 2, eps);
    diffusion<<<grid, 256>>>(A1, x,  2, 3, eps);

    // feature GEMM -> g_mid
    wgemm<<<ROWS / 64, 256>>>();

    // BN stats
    zero_stats<<<1, 64>>>();
    bn_stats<<<128, 256>>>();

    // BN + ReLU + FC -> out
    bn_relu_fc<<<512, 256>>>(gamma, beta, w2, b2, out);
}

// round 4
// speedup vs baseline: 5.4505x; 5.4505x over previous
#include <cuda_runtime.h>
#include <math.h>
#include <stdint.h>

// ---------------- problem dims ----------------
#define BB    32
#define NN    512
#define BD    768            // L*H
#define ROWS  (BB*NN)        // 16384
#define OUTC  64
#define KSUP  4
#define ZC    256            // KSUP*OUTC
#define AS    ((size_t)NN*NN)

// ---------------- device scratch (no allocation) ----------------
__device__ __align__(256) float g_M [2*AS];          // M_s = A_s + (1+eps)I
__device__ __align__(256) float g_M2[2*AS];          // M_s^2
__device__ __align__(256) float g_Wcat[BD*ZC];       // Wcat[d][k*64+o]
__device__ __align__(256) float g_Z[(size_t)ROWS*ZC];
__device__ __align__(256) float g_mid[(size_t)ROWS*OUTC];
__device__ float g_sum[OUTC], g_sumsq[OUTC];

// ---------------- prep kernels ----------------
__global__ void prep_M(const float* __restrict__ sup, const float* __restrict__ eps) {
    int idx = blockIdx.x * blockDim.x + threadIdx.x;
    if (idx >= 2 * (int)AS) return;
    int rest = idx & (int)(AS - 1);
    int n = rest >> 9, m = rest & 511;
    g_M[idx] = sup[idx] + ((n == m) ? (1.0f + eps[0]) : 0.0f);
}

// weight [l][m][o], m = h*4+k ; Wcat[d][k*64+o], d = l*64+h
__global__ void prep_W(const float* __restrict__ w) {
    int idx = blockIdx.x * blockDim.x + threadIdx.x;   // = d*256 + (k*64+o)
    if (idx >= BD * ZC) return;
    int ko = idx & 255;
    int d  = idx >> 8;
    int k = ko >> 6, o = ko & 63;
    int l = d >> 6, h = d & 63;
    g_Wcat[idx] = w[((size_t)l * 256 + h * 4 + k) * OUTC + o];
}

// ---------------- M^2: g_M2[s] = M_s * M_s  (64x64 tile, BK=16) ----------------
__global__ __launch_bounds__(256) void gemm_m2() {
    __shared__ float As[16][64];
    __shared__ float Bs[16][64];
    const int s  = blockIdx.z;
    const int n0 = blockIdx.y * 64;
    const int m0 = blockIdx.x * 64;
    const float* M = g_M + (size_t)s * AS;
    float* O = g_M2 + (size_t)s * AS;

    const int tid = threadIdx.x;
    const int tr = tid >> 4, tc = tid & 15;

    float acc[4][4];
#pragma unroll
    for (int i = 0; i < 4; ++i)
#pragma unroll
        for (int j = 0; j < 4; ++j) acc[i][j] = 0.f;

    for (int j0 = 0; j0 < NN; j0 += 16) {
#pragma unroll
        for (int t = 0; t < 4; ++t) {
            int idx = tid + t * 256;
            int i = idx >> 4, j = idx & 15;
            As[j][i] = M[(size_t)(n0 + i) * NN + j0 + j];
        }
#pragma unroll
        for (int t = 0; t < 4; ++t) {
            int idx = tid + t * 256;
            int j = idx >> 6, i = idx & 63;
            Bs[j][i] = M[(size_t)(j0 + j) * NN + m0 + i];
        }
        __syncthreads();
#pragma unroll
        for (int j = 0; j < 16; ++j) {
            float a[4], bv[4];
#pragma unroll
            for (int m = 0; m < 4; ++m) a[m] = As[j][tr * 4 + m];
#pragma unroll
            for (int n = 0; n < 4; ++n) bv[n] = Bs[j][tc * 4 + n];
#pragma unroll
            for (int m = 0; m < 4; ++m)
#pragma unroll
                for (int n = 0; n < 4; ++n)
                    acc[m][n] += a[m] * bv[n];
        }
        __syncthreads();
    }
#pragma unroll
    for (int m = 0; m < 4; ++m)
        *(float4*)&O[(size_t)(n0 + tr * 4 + m) * NN + m0 + tc * 4] =
            *(float4*)&acc[m][0];
}

// ---------------- stage1: Z[16384,256] = X[16384,768] * Wcat[768,256] -----------
// 128x128 tile, BK=8, 256 thr, 8x8 micro, register prefetch.
__global__ __launch_bounds__(256) void stage1(const float* __restrict__ X) {
    __shared__ float As[8][128];
    __shared__ float Bs[8][128];

    const int r0 = blockIdx.y * 128;
    const int c0 = blockIdx.x * 128;
    const int tid = threadIdx.x;
    const int tr = tid >> 4, tc = tid & 15;

    const int ai = tid >> 3, aj = tid & 7;      // A: rows ai + q*32, col aj
    const int bj = tid >> 7, bi = tid & 127;    // B: rows bj + q*2, col bi

    float acc[8][8];
#pragma unroll
    for (int i = 0; i < 8; ++i)
#pragma unroll
        for (int j = 0; j < 8; ++j) acc[i][j] = 0.f;

    float pa[4], pb[4];
    // prefetch k0 = 0
#pragma unroll
    for (int q = 0; q < 4; ++q)
        pa[q] = X[(size_t)(r0 + ai + q * 32) * BD + aj];
#pragma unroll
    for (int q = 0; q < 4; ++q)
        pb[q] = g_Wcat[(size_t)(bj + q * 2) * ZC + c0 + bi];

    for (int k0 = 0; k0 < BD; k0 += 8) {
#pragma unroll
        for (int q = 0; q < 4; ++q) As[aj][ai + q * 32] = pa[q];
#pragma unroll
        for (int q = 0; q < 4; ++q) Bs[bj + q * 2][bi] = pb[q];
        __syncthreads();

        if (k0 + 8 < BD) {
#pragma unroll
            for (int q = 0; q < 4; ++q)
                pa[q] = X[(size_t)(r0 + ai + q * 32) * BD + k0 + 8 + aj];
#pragma unroll
            for (int q = 0; q < 4; ++q)
                pb[q] = g_Wcat[(size_t)(k0 + 8 + bj + q * 2) * ZC + c0 + bi];
        }

#pragma unroll
        for (int j = 0; j < 8; ++j) {
            float4 a0 = *(const float4*)&As[j][tr * 8];
            float4 a1 = *(const float4*)&As[j][tr * 8 + 4];
            float4 b0 = *(const float4*)&Bs[j][tc * 8];
            float4 b1 = *(const float4*)&Bs[j][tc * 8 + 4];
            float av[8] = {a0.x, a0.y, a0.z, a0.w, a1.x, a1.y, a1.z, a1.w};
            float bv[8] = {b0.x, b0.y, b0.z, b0.w, b1.x, b1.y, b1.z, b1.w};
#pragma unroll
            for (int m = 0; m < 8; ++m)
#pragma unroll
                for (int n = 0; n < 8; ++n)
                    acc[m][n] += av[m] * bv[n];
        }
        __syncthreads();
    }

#pragma unroll
    for (int m = 0; m < 8; ++m) {
        int row = r0 + tr * 8 + m;
#pragma unroll
        for (int n = 0; n < 8; n += 4)
            *(float4*)&g_Z[(size_t)row * ZC + c0 + tc * 8 + n] = *(float4*)&acc[m][n];
    }
}

// ---------------- stage2: mid_b = sum_k M'_k * Z_b[:, 64k:64k+64] ----------------
// per CTA: 64 rows x 64 cols, K = 4 * 512.  grid (NN/64, BB)
__global__ __launch_bounds__(256) void stage2() {
    __shared__ float As[16][64];
    __shared__ float Bs[16][64];

    const int n0 = blockIdx.x * 64;
    const int b  = blockIdx.y;
    const int tid = threadIdx.x;
    const int tr = tid >> 4, tc = tid & 15;

    float acc[4][4];
#pragma unroll
    for (int i = 0; i < 4; ++i)
#pragma unroll
        for (int j = 0; j < 4; ++j) acc[i][j] = 0.f;

    const float* Zb = g_Z + ((size_t)b * NN) * ZC;

#pragma unroll
    for (int k = 0; k < KSUP; ++k) {
        const float* Mk = ((k & 1) ? g_M2 : g_M) + (size_t)(k >> 1) * AS;
        const float* Zk = Zb + k * OUTC;
        for (int m0 = 0; m0 < NN; m0 += 16) {
#pragma unroll
            for (int t = 0; t < 4; ++t) {
                int idx = tid + t * 256;
                int i = idx >> 4, j = idx & 15;
                As[j][i] = Mk[(size_t)(n0 + i) * NN + m0 + j];
            }
#pragma unroll
            for (int t = 0; t < 4; ++t) {
                int idx = tid + t * 256;
                int j = idx >> 6, i = idx & 63;
                Bs[j][i] = Zk[(size_t)(m0 + j) * ZC + i];
            }
            __syncthreads();
#pragma unroll
            for (int j = 0; j < 16; ++j) {
                float a[4], bv[4];
#pragma unroll
                for (int m = 0; m < 4; ++m) a[m] = As[j][tr * 4 + m];
#pragma unroll
                for (int n = 0; n < 4; ++n) bv[n] = Bs[j][tc * 4 + n];
#pragma unroll
                for (int m = 0; m < 4; ++m)
#pragma unroll
                    for (int n = 0; n < 4; ++n)
                        acc[m][n] += a[m] * bv[n];
            }
            __syncthreads();
        }
    }

#pragma unroll
    for (int m = 0; m < 4; ++m)
        *(float4*)&g_mid[(size_t)(b * NN + n0 + tr * 4 + m) * OUTC + tc * 4] =
            *(float4*)&acc[m][0];
}

// ---------------- BN tail ----------------
__global__ void zero_stats() {
    if (threadIdx.x < OUTC) { g_sum[threadIdx.x] = 0.f; g_sumsq[threadIdx.x] = 0.f; }
}
__global__ __launch_bounds__(256) void bn_stats() {
    const int c = threadIdx.x & 63;
    const int rl = threadIdx.x >> 6;
    float s = 0.f, s2 = 0.f;
    for (int r = blockIdx.x * 4 + rl; r < ROWS; r += gridDim.x * 4) {
        float v = g_mid[(size_t)r * OUTC + c];
        s += v; s2 += v * v;
    }
    __shared__ float sh[256], sh2[256];
    sh[threadIdx.x] = s; sh2[threadIdx.x] = s2;
    __syncthreads();
    if (rl == 0) {
        s  = sh[c] + sh[c + 64] + sh[c + 128] + sh[c + 192];
        s2 = sh2[c] + sh2[c + 64] + sh2[c + 128] + sh2[c + 192];
        atomicAdd(&g_sum[c], s); atomicAdd(&g_sumsq[c], s2);
    }
}
__global__ __launch_bounds__(256) void bn_relu_fc(
    const float* __restrict__ gamma, const float* __restrict__ beta,
    const float* __restrict__ w2,    const float* __restrict__ b2,
    float* __restrict__ out)
{
    __shared__ float w2t[64][65];
    __shared__ float scale_s[64], shift_s[64];
    __shared__ float y[4][64];
    const int tid = threadIdx.x;
#pragma unroll
    for (int t = 0; t < 16; ++t) {
        int idx = tid + t * 256;
        int o = idx >> 6, c = idx & 63;
        w2t[c][o] = w2[idx];
    }
    if (tid < OUTC) {
        const float invN = 1.0f / (float)ROWS;
        float mean = g_sum[tid] * invN;
        float var  = g_sumsq[tid] * invN - mean * mean;
        float sc   = gamma[tid] * rsqrtf(var + 1e-5f);
        scale_s[tid] = sc;
        shift_s[tid] = beta[tid] - mean * sc;
    }
    __syncthreads();
    const int rl = tid >> 6, c = tid & 63;
    for (int r0 = blockIdx.x * 4; r0 < ROWS; r0 += gridDim.x * 4) {
        int r = r0 + rl;
        float v = g_mid[(size_t)r * OUTC + c];
        v = fmaxf(fmaf(v, scale_s[c], shift_s[c]), 0.f);
        y[rl][c] = v;
        __syncthreads();
        float acc = b2[c];
#pragma unroll
        for (int cc = 0; cc < 64; ++cc)
            acc = fmaf(y[rl][cc], w2t[cc][c], acc);
        out[(size_t)r * OUTC + c] = acc;
        __syncthreads();
    }
}

// ---------------- launch ----------------
extern "C" void kernel_launch(void* const* d_in, const int* in_sizes, int n_in,
                              void* d_out, int out_size) {
    const float* x       = (const float*)d_in[0];   // [32,512,12,64]
    const float* support = (const float*)d_in[1];   // [2,512,512]
    const float* weight  = (const float*)d_in[2];   // [12,256,64]
    const float* eps     = (const float*)d_in[3];   // [1]
    const float* gamma   = (const float*)d_in[4];   // [64]
    const float* beta    = (const float*)d_in[5];   // [64]
    const float* w2      = (const float*)d_in[6];   // [64,64]
    const float* b2      = (const float*)d_in[7];   // [64]
    float* out           = (float*)d_out;           // [32,512,64]

    prep_M<<<(2 * (int)AS + 255) / 256, 256>>>(support, eps);
    prep_W<<<(BD * ZC + 255) / 256, 256>>>(weight);

    gemm_m2<<<dim3(NN / 64, NN / 64, 2), 256>>>();

    stage1<<<dim3(ZC / 128, ROWS / 128), 256>>>(x);

    stage2<<<dim3(NN / 64, BB), 256>>>();

    zero_stats<<<1, 64>>>();
    bn_stats<<<128, 256>>>();
    bn_relu_fc<<<512, 256>>>(gamma, beta, w2, b2, out);
}

// round 5
// speedup vs baseline: 6.7679x; 1.2417x over previous
#include <cuda_runtime.h>
#include <cuda_bf16.h>
#include <math.h>
#include <stdint.h>

typedef __nv_bfloat16 bf16;

// ---------------- problem dims ----------------
#define BB    32
#define NN    512
#define BD    768            // L*H
#define ROWS  (BB*NN)        // 16384
#define OUTC  64
#define KSUP  4
#define ZC    256            // KSUP*OUTC
#define AS    ((size_t)NN*NN)

// ---------------- device scratch (no allocation) ----------------
__device__ __align__(256) float g_M [2*AS];          // M_s = A_s + (1+eps)I
__device__ __align__(256) float g_M2[2*AS];          // M_s^2
__device__ __align__(256) bf16  g_Xh[(size_t)ROWS*BD], g_Xl[(size_t)ROWS*BD];
__device__ __align__(256) bf16  g_Wth[ZC*BD], g_Wtl[ZC*BD];   // W^T repack [ko][d]
__device__ __align__(256) float g_Z[(size_t)ROWS*ZC];
__device__ __align__(256) float g_mid[(size_t)ROWS*OUTC];
__device__ float g_sum[OUTC], g_sumsq[OUTC];

__device__ __forceinline__ uint32_t smem_u32(const void* p) {
    uint32_t a;
    asm("{ .reg .u64 t; cvta.to.shared.u64 t, %1; cvt.u32.u64 %0, t; }" : "=r"(a) : "l"(p));
    return a;
}
__device__ __forceinline__ void split_bf16(float v, bf16& h, bf16& l) {
    h = __float2bfloat16(v);
    l = __float2bfloat16(v - __bfloat162float(h));
}
__device__ __forceinline__ uint32_t pack2(bf16 lo, bf16 hi) {
    return ((uint32_t)__bfloat16_as_ushort(hi) << 16) | __bfloat16_as_ushort(lo);
}

// ---------------- prep kernels ----------------
__global__ void prep_M(const float* __restrict__ sup, const float* __restrict__ eps) {
    int idx = blockIdx.x * blockDim.x + threadIdx.x;
    if (idx >= 2 * (int)AS) return;
    int rest = idx & (int)(AS - 1);
    int n = rest >> 9, m = rest & 511;
    g_M[idx] = sup[idx] + ((n == m) ? (1.0f + eps[0]) : 0.0f);
}

// weight [l][m][o], m=h*4+k  ->  g_Wt{h,l}[ko][d], ko=k*64+o, d=l*64+h
__global__ void prep_W(const float* __restrict__ w) {
    int idx = blockIdx.x * blockDim.x + threadIdx.x;   // ko*768 + d
    if (idx >= ZC * BD) return;
    int d  = idx % BD;
    int ko = idx / BD;
    int k = ko >> 6, o = ko & 63;
    int l = d >> 6, h = d & 63;
    float v = w[((size_t)l * 256 + h * 4 + k) * OUTC + o];
    bf16 hh, ll; split_bf16(v, hh, ll);
    g_Wth[idx] = hh; g_Wtl[idx] = ll;
}

__global__ void split_X(const float* __restrict__ x) {
    int idx = blockIdx.x * blockDim.x + threadIdx.x;
    if (idx >= (int)(ROWS * (size_t)BD / 4)) return;
    float4 v = ((const float4*)x)[idx];
    bf16 h0,l0,h1,l1,h2,l2,h3,l3;
    split_bf16(v.x,h0,l0); split_bf16(v.y,h1,l1);
    split_bf16(v.z,h2,l2); split_bf16(v.w,h3,l3);
    uint2 ph, pl;
    ph.x = pack2(h0,h1); ph.y = pack2(h2,h3);
    pl.x = pack2(l0,l1); pl.y = pack2(l2,l3);
    ((uint2*)g_Xh)[idx] = ph;
    ((uint2*)g_Xl)[idx] = pl;
}

// ---------------- M^2 (unchanged, passing) ----------------
__global__ __launch_bounds__(256) void gemm_m2() {
    __shared__ float As[16][64];
    __shared__ float Bs[16][64];
    const int s  = blockIdx.z;
    const int n0 = blockIdx.y * 64;
    const int m0 = blockIdx.x * 64;
    const float* M = g_M + (size_t)s * AS;
    float* O = g_M2 + (size_t)s * AS;

    const int tid = threadIdx.x;
    const int tr = tid >> 4, tc = tid & 15;

    float acc[4][4];
#pragma unroll
    for (int i = 0; i < 4; ++i)
#pragma unroll
        for (int j = 0; j < 4; ++j) acc[i][j] = 0.f;

    for (int j0 = 0; j0 < NN; j0 += 16) {
#pragma unroll
        for (int t = 0; t < 4; ++t) {
            int idx = tid + t * 256;
            int i = idx >> 4, j = idx & 15;
            As[j][i] = M[(size_t)(n0 + i) * NN + j0 + j];
        }
#pragma unroll
        for (int t = 0; t < 4; ++t) {
            int idx = tid + t * 256;
            int j = idx >> 6, i = idx & 63;
            Bs[j][i] = M[(size_t)(j0 + j) * NN + m0 + i];
        }
        __syncthreads();
#pragma unroll
        for (int j = 0; j < 16; ++j) {
            float a[4], bv[4];
#pragma unroll
            for (int m = 0; m < 4; ++m) a[m] = As[j][tr * 4 + m];
#pragma unroll
            for (int n = 0; n < 4; ++n) bv[n] = Bs[j][tc * 4 + n];
#pragma unroll
            for (int m = 0; m < 4; ++m)
#pragma unroll
                for (int n = 0; n < 4; ++n)
                    acc[m][n] += a[m] * bv[n];
        }
        __syncthreads();
    }
#pragma unroll
    for (int m = 0; m < 4; ++m)
        *(float4*)&O[(size_t)(n0 + tr * 4 + m) * NN + m0 + tc * 4] =
            *(float4*)&acc[m][0];
}

// ---------------- stage1 (tensor-core): Z = Xh*Wh + Xl*Wh + Xh*Wl ----------------
// CTA 128x128, 8 warps (32x64 each), BK=32 bf16, double-buffered, ldmatrix + mma.sync
#define S1_PAD 40            // bf16 elems per smem row (80 B, 16B-multiple, conflict-free)
#define S1_NCHUNK 72         // 3 parts * 768/32

__global__ __launch_bounds__(256) void stage1_mma() {
    __shared__ __align__(16) bf16 As_[2][128 * S1_PAD];
    __shared__ __align__(16) bf16 Bs_[2][128 * S1_PAD];

    const int tid = threadIdx.x;
    const int warp = tid >> 5, lane = tid & 31;
    const int wm = warp >> 1, wn = warp & 1;
    const int g = lane >> 2, q = lane & 3;
    const int r0 = blockIdx.y * 128;     // rows (ROWS/128 = 128)
    const int c0 = blockIdx.x * 128;     // cols (ZC/128 = 2)

    const int ldrow = tid >> 2;          // 0..63 per 256-group step
    const int ldseg = tid & 3;

    // lane-invariant ldmatrix offsets
    const int aRowOff = ((lane >> 3) & 1) * 8 + (lane & 7);
    const int aKOff   = (lane >> 4) * 8;
    const int bRowOff = (lane >> 4) * 8 + (lane & 7);
    const int bKOff   = ((lane >> 3) & 1) * 8;

    uint32_t aBase[2] = { smem_u32(&As_[0][0]), smem_u32(&As_[1][0]) };
    uint32_t bBase[2] = { smem_u32(&Bs_[0][0]), smem_u32(&Bs_[1][0]) };

    float c[2][8][4];
#pragma unroll
    for (int i = 0; i < 2; ++i)
#pragma unroll
        for (int j = 0; j < 8; ++j)
#pragma unroll
            for (int t = 0; t < 4; ++t) c[i][j][t] = 0.f;

    uint4 pa[2], pb[2];
    auto ldg = [&](int ch) {
        int part = ch / 24;
        int kpos = (ch % 24) * 32;
        const bf16* Ap = (part == 1) ? g_Xl : g_Xh;
        const bf16* Bp = (part == 2) ? g_Wtl : g_Wth;
#pragma unroll
        for (int t = 0; t < 2; ++t) {
            int row = ldrow + t * 64;
            pa[t] = *(const uint4*)(Ap + (size_t)(r0 + row) * BD + kpos + ldseg * 8);
            pb[t] = *(const uint4*)(Bp + (size_t)(c0 + row) * BD + kpos + ldseg * 8);
        }
    };
    auto sts = [&](int buf) {
#pragma unroll
        for (int t = 0; t < 2; ++t) {
            int row = ldrow + t * 64;
            *(uint4*)(&As_[buf][row * S1_PAD + ldseg * 8]) = pa[t];
            *(uint4*)(&Bs_[buf][row * S1_PAD + ldseg * 8]) = pb[t];
        }
    };

    ldg(0); sts(0);
    __syncthreads();

    for (int ch = 0; ch < S1_NCHUNK; ++ch) {
        int buf = ch & 1;
        if (ch + 1 < S1_NCHUNK) ldg(ch + 1);

#pragma unroll
        for (int ks = 0; ks < 32; ks += 16) {
            uint32_t a[2][4];
#pragma unroll
            for (int i = 0; i < 2; ++i) {
                uint32_t addr = aBase[buf]
                    + (uint32_t)(wm * 32 + i * 16 + aRowOff) * (S1_PAD * 2)
                    + (uint32_t)(ks + aKOff) * 2;
                asm volatile("ldmatrix.sync.aligned.m8n8.x4.shared.b16 {%0,%1,%2,%3}, [%4];"
                             : "=r"(a[i][0]), "=r"(a[i][1]), "=r"(a[i][2]), "=r"(a[i][3])
                             : "r"(addr));
            }
            uint32_t b[8][2];
#pragma unroll
            for (int j2 = 0; j2 < 4; ++j2) {
                uint32_t addr = bBase[buf]
                    + (uint32_t)(wn * 64 + j2 * 16 + bRowOff) * (S1_PAD * 2)
                    + (uint32_t)(ks + bKOff) * 2;
                uint32_t r0_, r1_, r2_, r3_;
                asm volatile("ldmatrix.sync.aligned.m8n8.x4.shared.b16 {%0,%1,%2,%3}, [%4];"
                             : "=r"(r0_), "=r"(r1_), "=r"(r2_), "=r"(r3_)
                             : "r"(addr));
                b[2*j2][0]   = r0_; b[2*j2][1]   = r1_;
                b[2*j2+1][0] = r2_; b[2*j2+1][1] = r3_;
            }
#pragma unroll
            for (int i = 0; i < 2; ++i)
#pragma unroll
                for (int j = 0; j < 8; ++j)
                    asm volatile(
                        "mma.sync.aligned.m16n8k16.row.col.f32.bf16.bf16.f32 "
                        "{%0,%1,%2,%3}, {%4,%5,%6,%7}, {%8,%9}, {%0,%1,%2,%3};"
                        : "+f"(c[i][j][0]), "+f"(c[i][j][1]), "+f"(c[i][j][2]), "+f"(c[i][j][3])
                        : "r"(a[i][0]), "r"(a[i][1]), "r"(a[i][2]), "r"(a[i][3]),
                          "r"(b[j][0]), "r"(b[j][1]));
        }
        if (ch + 1 < S1_NCHUNK) sts((ch + 1) & 1);
        __syncthreads();
    }

    // epilogue: fp32 -> g_Z
#pragma unroll
    for (int i = 0; i < 2; ++i) {
        int row = r0 + wm * 32 + i * 16 + g;
#pragma unroll
        for (int j = 0; j < 8; ++j) {
            int col = c0 + wn * 64 + j * 8 + 2 * q;
            float2 v0 = { c[i][j][0], c[i][j][1] };
            float2 v1 = { c[i][j][2], c[i][j][3] };
            *(float2*)&g_Z[(size_t)row * ZC + col] = v0;
            *(float2*)&g_Z[(size_t)(row + 8) * ZC + col] = v1;
        }
    }
}

// ---------------- stage2 (unchanged, passing) ----------------
__global__ __launch_bounds__(256) void stage2() {
    __shared__ float As[16][64];
    __shared__ float Bs[16][64];

    const int n0 = blockIdx.x * 64;
    const int b  = blockIdx.y;
    const int tid = threadIdx.x;
    const int tr = tid >> 4, tc = tid & 15;

    float acc[4][4];
#pragma unroll
    for (int i = 0; i < 4; ++i)
#pragma unroll
        for (int j = 0; j < 4; ++j) acc[i][j] = 0.f;

    const float* Zb = g_Z + ((size_t)b * NN) * ZC;

#pragma unroll
    for (int k = 0; k < KSUP; ++k) {
        const float* Mk = ((k & 1) ? g_M2 : g_M) + (size_t)(k >> 1) * AS;
        const float* Zk = Zb + k * OUTC;
        for (int m0 = 0; m0 < NN; m0 += 16) {
#pragma unroll
            for (int t = 0; t < 4; ++t) {
                int idx = tid + t * 256;
                int i = idx >> 4, j = idx & 15;
                As[j][i] = Mk[(size_t)(n0 + i) * NN + m0 + j];
            }
#pragma unroll
            for (int t = 0; t < 4; ++t) {
                int idx = tid + t * 256;
                int j = idx >> 6, i = idx & 63;
                Bs[j][i] = Zk[(size_t)(m0 + j) * ZC + i];
            }
            __syncthreads();
#pragma unroll
            for (int j = 0; j < 16; ++j) {
                float a[4], bv[4];
#pragma unroll
                for (int m = 0; m < 4; ++m) a[m] = As[j][tr * 4 + m];
#pragma unroll
                for (int n = 0; n < 4; ++n) bv[n] = Bs[j][tc * 4 + n];
#pragma unroll
                for (int m = 0; m < 4; ++m)
#pragma unroll
                    for (int n = 0; n < 4; ++n)
                        acc[m][n] += a[m] * bv[n];
            }
            __syncthreads();
        }
    }

#pragma unroll
    for (int m = 0; m < 4; ++m)
        *(float4*)&g_mid[(size_t)(b * NN + n0 + tr * 4 + m) * OUTC + tc * 4] =
            *(float4*)&acc[m][0];
}

// ---------------- BN tail (unchanged, passing) ----------------
__global__ void zero_stats() {
    if (threadIdx.x < OUTC) { g_sum[threadIdx.x] = 0.f; g_sumsq[threadIdx.x] = 0.f; }
}
__global__ __launch_bounds__(256) void bn_stats() {
    const int c = threadIdx.x & 63;
    const int rl = threadIdx.x >> 6;
    float s = 0.f, s2 = 0.f;
    for (int r = blockIdx.x * 4 + rl; r < ROWS; r += gridDim.x * 4) {
        float v = g_mid[(size_t)r * OUTC + c];
        s += v; s2 += v * v;
    }
    __shared__ float sh[256], sh2[256];
    sh[threadIdx.x] = s; sh2[threadIdx.x] = s2;
    __syncthreads();
    if (rl == 0) {
        s  = sh[c] + sh[c + 64] + sh[c + 128] + sh[c + 192];
        s2 = sh2[c] + sh2[c + 64] + sh2[c + 128] + sh2[c + 192];
        atomicAdd(&g_sum[c], s); atomicAdd(&g_sumsq[c], s2);
    }
}
__global__ __launch_bounds__(256) void bn_relu_fc(
    const float* __restrict__ gamma, const float* __restrict__ beta,
    const float* __restrict__ w2,    const float* __restrict__ b2,
    float* __restrict__ out)
{
    __shared__ float w2t[64][65];
    __shared__ float scale_s[64], shift_s[64];
    __shared__ float y[4][64];
    const int tid = threadIdx.x;
#pragma unroll
    for (int t = 0; t < 16; ++t) {
        int idx = tid + t * 256;
        int o = idx >> 6, c = idx & 63;
        w2t[c][o] = w2[idx];
    }
    if (tid < OUTC) {
        const float invN = 1.0f / (float)ROWS;
        float mean = g_sum[tid] * invN;
        float var  = g_sumsq[tid] * invN - mean * mean;
        float sc   = gamma[tid] * rsqrtf(var + 1e-5f);
        scale_s[tid] = sc;
        shift_s[tid] = beta[tid] - mean * sc;
    }
    __syncthreads();
    const int rl = tid >> 6, c = tid & 63;
    for (int r0 = blockIdx.x * 4; r0 < ROWS; r0 += gridDim.x * 4) {
        int r = r0 + rl;
        float v = g_mid[(size_t)r * OUTC + c];
        v = fmaxf(fmaf(v, scale_s[c], shift_s[c]), 0.f);
        y[rl][c] = v;
        __syncthreads();
        float acc = b2[c];
#pragma unroll
        for (int cc = 0; cc < 64; ++cc)
            acc = fmaf(y[rl][cc], w2t[cc][c], acc);
        out[(size_t)r * OUTC + c] = acc;
        __syncthreads();
    }
}

// ---------------- launch ----------------
extern "C" void kernel_launch(void* const* d_in, const int* in_sizes, int n_in,
                              void* d_out, int out_size) {
    const float* x       = (const float*)d_in[0];
    const float* support = (const float*)d_in[1];
    const float* weight  = (const float*)d_in[2];
    const float* eps     = (const float*)d_in[3];
    const float* gamma   = (const float*)d_in[4];
    const float* beta    = (const float*)d_in[5];
    const float* w2      = (const float*)d_in[6];
    const float* b2      = (const float*)d_in[7];
    float* out           = (float*)d_out;

    prep_M<<<(2 * (int)AS + 255) / 256, 256>>>(support, eps);
    prep_W<<<(ZC * BD + 255) / 256, 256>>>(weight);
    split_X<<<(int)(ROWS * (size_t)BD / 4 + 255) / 256, 256>>>(x);

    gemm_m2<<<dim3(NN / 64, NN / 64, 2), 256>>>();

    stage1_mma<<<dim3(ZC / 128, ROWS / 128), 256>>>();

    stage2<<<dim3(NN / 64, BB), 256>>>();

    zero_stats<<<1, 64>>>();
    bn_stats<<<128, 256>>>();
    bn_relu_fc<<<512, 256>>>(gamma, beta, w2, b2, out);
}

// round 7
// speedup vs baseline: 9.3960x; 1.3883x over previous
#include <cuda_runtime.h>
#include <cuda_bf16.h>
#include <math.h>
#include <stdint.h>

typedef __nv_bfloat16 bf16;

// ---------------- problem dims ----------------
#define BB    32
#define NN    512
#define BD    768            // L*H
#define ROWS  (BB*NN)        // 16384
#define OUTC  64
#define KSUP  4
#define ZC    256            // KSUP*OUTC
#define AS    ((size_t)NN*NN)

// ---------------- device scratch (no allocation) ----------------
__device__ __align__(256) bf16  g_Mh [2*AS], g_Ml [2*AS];    // M = A+(1+eps)I, split
__device__ __align__(256) bf16  g_M2h[2*AS], g_M2l[2*AS];    // M^2, split
__device__ __align__(256) bf16  g_Xh[(size_t)ROWS*BD], g_Xl[(size_t)ROWS*BD];
__device__ __align__(256) bf16  g_Wth[ZC*BD], g_Wtl[ZC*BD];  // W^T repack [ko][d]
__device__ __align__(256) bf16  g_Zh[(size_t)ROWS*ZC], g_Zl[(size_t)ROWS*ZC];
__device__ __align__(256) float g_mid[(size_t)ROWS*OUTC];
__device__ float g_sum[OUTC], g_sumsq[OUTC];

__device__ __forceinline__ uint32_t smem_u32(const void* p) {
    uint32_t a;
    asm("{ .reg .u64 t; cvta.to.shared.u64 t, %1; cvt.u32.u64 %0, t; }" : "=r"(a) : "l"(p));
    return a;
}
__device__ __forceinline__ void split_bf16(float v, bf16& h, bf16& l) {
    h = __float2bfloat16(v);
    l = __float2bfloat16(v - __bfloat162float(h));
}
__device__ __forceinline__ uint32_t pack2(bf16 lo, bf16 hi) {
    return ((uint32_t)__bfloat16_as_ushort(hi) << 16) | __bfloat16_as_ushort(lo);
}

#define LDSM_X4(r0,r1,r2,r3,addr) \
    asm volatile("ldmatrix.sync.aligned.m8n8.x4.shared.b16 {%0,%1,%2,%3}, [%4];" \
                 : "=r"(r0), "=r"(r1), "=r"(r2), "=r"(r3) : "r"(addr))
#define LDSM_X4T(r0,r1,r2,r3,addr) \
    asm volatile("ldmatrix.sync.aligned.m8n8.x4.trans.shared.b16 {%0,%1,%2,%3}, [%4];" \
                 : "=r"(r0), "=r"(r1), "=r"(r2), "=r"(r3) : "r"(addr))
#define MMA_BF16(c0,c1,c2,c3,a0,a1,a2,a3,b0,b1) \
    asm volatile("mma.sync.aligned.m16n8k16.row.col.f32.bf16.bf16.f32 " \
                 "{%0,%1,%2,%3}, {%4,%5,%6,%7}, {%8,%9}, {%0,%1,%2,%3};" \
                 : "+f"(c0), "+f"(c1), "+f"(c2), "+f"(c3) \
                 : "r"(a0), "r"(a1), "r"(a2), "r"(a3), "r"(b0), "r"(b1))

// ---------------- prep kernels ----------------
__global__ void prep_M(const float* __restrict__ sup, const float* __restrict__ eps) {
    int idx = blockIdx.x * blockDim.x + threadIdx.x;
    if (idx >= 2 * (int)AS) return;
    int rest = idx & (int)(AS - 1);
    int n = rest >> 9, m = rest & 511;
    float v = sup[idx] + ((n == m) ? (1.0f + eps[0]) : 0.0f);
    bf16 h, l; split_bf16(v, h, l);
    g_Mh[idx] = h; g_Ml[idx] = l;
}

// weight [l][m][o], m=h*4+k  ->  g_Wt{h,l}[ko][d], ko=k*64+o, d=l*64+h
__global__ void prep_W(const float* __restrict__ w) {
    int idx = blockIdx.x * blockDim.x + threadIdx.x;   // ko*768 + d
    if (idx >= ZC * BD) return;
    int d  = idx % BD;
    int ko = idx / BD;
    int k = ko >> 6, o = ko & 63;
    int l = d >> 6, h = d & 63;
    float v = w[((size_t)l * 256 + h * 4 + k) * OUTC + o];
    bf16 hh, ll; split_bf16(v, hh, ll);
    g_Wth[idx] = hh; g_Wtl[idx] = ll;
}

__global__ void split_X(const float* __restrict__ x) {
    int idx = blockIdx.x * blockDim.x + threadIdx.x;
    if (idx >= (int)(ROWS * (size_t)BD / 4)) return;
    float4 v = ((const float4*)x)[idx];
    bf16 h0,l0,h1,l1,h2,l2,h3,l3;
    split_bf16(v.x,h0,l0); split_bf16(v.y,h1,l1);
    split_bf16(v.z,h2,l2); split_bf16(v.w,h3,l3);
    uint2 ph, pl;
    ph.x = pack2(h0,h1); ph.y = pack2(h2,h3);
    pl.x = pack2(l0,l1); pl.y = pack2(l2,l3);
    ((uint2*)g_Xh)[idx] = ph;
    ((uint2*)g_Xl)[idx] = pl;
}

// ---------------- M^2 (HMMA): M2 = Mh*Mh + Ml*Mh + Mh*Ml, split output -----------
// CTA 128n x 64m, 8 warps (wm 0..3 x 32 rows, wn 0..1 x 32 cols), BK=32
#define M2_APAD 40
#define M2_BPAD 72
#define M2_NCHUNK 48      // 3 parts * 512/32

__global__ __launch_bounds__(256) void gemm_m2_mma() {
    __shared__ __align__(16) bf16 As_[2][128 * M2_APAD];
    __shared__ __align__(16) bf16 Bs_[2][32 * M2_BPAD];

    const int tid = threadIdx.x;
    const int warp = tid >> 5, lane = tid & 31;
    const int wm = warp >> 1, wn = warp & 1;
    const int g = lane >> 2, q = lane & 3;
    const int s  = blockIdx.z;
    const int n0 = blockIdx.y * 128;
    const int m0 = blockIdx.x * 64;

    const int aLdRow = tid >> 2, aLdSeg = tid & 3;   // A: 128x32
    const int bLdRow = tid >> 3, bLdSeg = tid & 7;   // B: 32x64
    const int fragRow  = lane & 15;
    const int fragCol8 = (lane >> 4) * 8;

    uint32_t aBase[2] = { smem_u32(&As_[0][0]), smem_u32(&As_[1][0]) };
    uint32_t bBase[2] = { smem_u32(&Bs_[0][0]), smem_u32(&Bs_[1][0]) };

    const bf16* Mh = g_Mh + (size_t)s * AS;
    const bf16* Ml = g_Ml + (size_t)s * AS;

    float c[2][4][4];
#pragma unroll
    for (int i = 0; i < 2; ++i)
#pragma unroll
        for (int j = 0; j < 4; ++j)
#pragma unroll
            for (int t = 0; t < 4; ++t) c[i][j][t] = 0.f;

    uint4 pa[2], pb;
    auto ldg = [&](int ch) {
        int part = ch >> 4;
        int jpos = (ch & 15) * 32;
        const bf16* Ap = (part == 1) ? Ml : Mh;
        const bf16* Bp = (part == 2) ? Ml : Mh;
        pa[0] = *(const uint4*)(Ap + (size_t)(n0 + aLdRow) * NN + jpos + aLdSeg * 8);
        pa[1] = *(const uint4*)(Ap + (size_t)(n0 + aLdRow + 64) * NN + jpos + aLdSeg * 8);
        pb    = *(const uint4*)(Bp + (size_t)(jpos + bLdRow) * NN + m0 + bLdSeg * 8);
    };
    auto sts = [&](int buf) {
        *(uint4*)(&As_[buf][aLdRow * M2_APAD + aLdSeg * 8]) = pa[0];
        *(uint4*)(&As_[buf][(aLdRow + 64) * M2_APAD + aLdSeg * 8]) = pa[1];
        *(uint4*)(&Bs_[buf][bLdRow * M2_BPAD + bLdSeg * 8]) = pb;
    };

    ldg(0); sts(0);
    __syncthreads();

    for (int ch = 0; ch < M2_NCHUNK; ++ch) {
        int buf = ch & 1;
        if (ch + 1 < M2_NCHUNK) ldg(ch + 1);
#pragma unroll
        for (int ks = 0; ks < 32; ks += 16) {
            uint32_t a[2][4];
#pragma unroll
            for (int i = 0; i < 2; ++i) {
                uint32_t addr = aBase[buf]
                    + (uint32_t)(wm * 32 + i * 16 + fragRow) * (M2_APAD * 2)
                    + (uint32_t)(ks + fragCol8) * 2;
                LDSM_X4(a[i][0], a[i][1], a[i][2], a[i][3], addr);
            }
            uint32_t b[4][2];
#pragma unroll
            for (int jj = 0; jj < 2; ++jj) {
                uint32_t addr = bBase[buf]
                    + (uint32_t)(ks + fragRow) * (M2_BPAD * 2)
                    + (uint32_t)(wn * 32 + jj * 16 + fragCol8) * 2;
                uint32_t r0_, r1_, r2_, r3_;
                LDSM_X4T(r0_, r1_, r2_, r3_, addr);
                b[2*jj][0] = r0_;   b[2*jj][1] = r1_;
                b[2*jj+1][0] = r2_; b[2*jj+1][1] = r3_;
            }
#pragma unroll
            for (int i = 0; i < 2; ++i)
#pragma unroll
                for (int j = 0; j < 4; ++j)
                    MMA_BF16(c[i][j][0], c[i][j][1], c[i][j][2], c[i][j][3],
                             a[i][0], a[i][1], a[i][2], a[i][3], b[j][0], b[j][1]);
        }
        if (ch + 1 < M2_NCHUNK) sts((ch + 1) & 1);
        __syncthreads();
    }

    bf16* M2h = g_M2h + (size_t)s * AS;
    bf16* M2l = g_M2l + (size_t)s * AS;
#pragma unroll
    for (int i = 0; i < 2; ++i) {
        int row = n0 + wm * 32 + i * 16 + g;
#pragma unroll
        for (int j = 0; j < 4; ++j) {
            int col = m0 + wn * 32 + j * 8 + 2 * q;
#pragma unroll
            for (int hrow = 0; hrow < 2; ++hrow) {
                float v0 = c[i][j][hrow * 2], v1 = c[i][j][hrow * 2 + 1];
                bf16 h0, l0, h1, l1;
                split_bf16(v0, h0, l0); split_bf16(v1, h1, l1);
                size_t off = (size_t)(row + hrow * 8) * NN + col;
                *(uint32_t*)&M2h[off] = pack2(h0, h1);
                *(uint32_t*)&M2l[off] = pack2(l0, l1);
            }
        }
    }
}

// ---------------- stage1 (HMMA): Z = Xh*Wh + Xl*Wh + Xh*Wl, bf16-split output ----
// EXACT round-5 loader/fragment addressing (validated); only epilogue differs.
#define S1_PAD 40
#define S1_NCHUNK 72         // 3 parts * 768/32

__global__ __launch_bounds__(256) void stage1_mma() {
    __shared__ __align__(16) bf16 As_[2][128 * S1_PAD];
    __shared__ __align__(16) bf16 Bs_[2][128 * S1_PAD];

    const int tid = threadIdx.x;
    const int warp = tid >> 5, lane = tid & 31;
    const int wm = warp >> 1, wn = warp & 1;
    const int g = lane >> 2, q = lane & 3;
    const int r0 = blockIdx.y * 128;
    const int c0 = blockIdx.x * 128;

    const int ldrow = tid >> 2;
    const int ldseg = tid & 3;

    // round-5 validated lane-invariant ldmatrix offsets
    const int aRowOff = ((lane >> 3) & 1) * 8 + (lane & 7);
    const int aKOff   = (lane >> 4) * 8;
    const int bRowOff = (lane >> 4) * 8 + (lane & 7);
    const int bKOff   = ((lane >> 3) & 1) * 8;

    uint32_t aBase[2] = { smem_u32(&As_[0][0]), smem_u32(&As_[1][0]) };
    uint32_t bBase[2] = { smem_u32(&Bs_[0][0]), smem_u32(&Bs_[1][0]) };

    float c[2][8][4];
#pragma unroll
    for (int i = 0; i < 2; ++i)
#pragma unroll
        for (int j = 0; j < 8; ++j)
#pragma unroll
            for (int t = 0; t < 4; ++t) c[i][j][t] = 0.f;

    uint4 pa[2], pb[2];
    auto ldg = [&](int ch) {
        int part = ch / 24;
        int kpos = (ch % 24) * 32;
        const bf16* Ap = (part == 1) ? g_Xl : g_Xh;
        const bf16* Bp = (part == 2) ? g_Wtl : g_Wth;
#pragma unroll
        for (int t = 0; t < 2; ++t) {
            int row = ldrow + t * 64;
            pa[t] = *(const uint4*)(Ap + (size_t)(r0 + row) * BD + kpos + ldseg * 8);
            pb[t] = *(const uint4*)(Bp + (size_t)(c0 + row) * BD + kpos + ldseg * 8);
        }
    };
    auto sts = [&](int buf) {
#pragma unroll
        for (int t = 0; t < 2; ++t) {
            int row = ldrow + t * 64;
            *(uint4*)(&As_[buf][row * S1_PAD + ldseg * 8]) = pa[t];
            *(uint4*)(&Bs_[buf][row * S1_PAD + ldseg * 8]) = pb[t];
        }
    };

    ldg(0); sts(0);
    __syncthreads();

    for (int ch = 0; ch < S1_NCHUNK; ++ch) {
        int buf = ch & 1;
        if (ch + 1 < S1_NCHUNK) ldg(ch + 1);

#pragma unroll
        for (int ks = 0; ks < 32; ks += 16) {
            uint32_t a[2][4];
#pragma unroll
            for (int i = 0; i < 2; ++i) {
                uint32_t addr = aBase[buf]
                    + (uint32_t)(wm * 32 + i * 16 + aRowOff) * (S1_PAD * 2)
                    + (uint32_t)(ks + aKOff) * 2;
                LDSM_X4(a[i][0], a[i][1], a[i][2], a[i][3], addr);
            }
            uint32_t b[8][2];
#pragma unroll
            for (int j2 = 0; j2 < 4; ++j2) {
                uint32_t addr = bBase[buf]
                    + (uint32_t)(wn * 64 + j2 * 16 + bRowOff) * (S1_PAD * 2)
                    + (uint32_t)(ks + bKOff) * 2;
                uint32_t r0_, r1_, r2_, r3_;
                LDSM_X4(r0_, r1_, r2_, r3_, addr);
                b[2*j2][0]   = r0_; b[2*j2][1]   = r1_;
                b[2*j2+1][0] = r2_; b[2*j2+1][1] = r3_;
            }
#pragma unroll
            for (int i = 0; i < 2; ++i)
#pragma unroll
                for (int j = 0; j < 8; ++j)
                    MMA_BF16(c[i][j][0], c[i][j][1], c[i][j][2], c[i][j][3],
                             a[i][0], a[i][1], a[i][2], a[i][3], b[j][0], b[j][1]);
        }
        if (ch + 1 < S1_NCHUNK) sts((ch + 1) & 1);
        __syncthreads();
    }

    // epilogue: split fp32 -> Zh/Zl bf16
#pragma unroll
    for (int i = 0; i < 2; ++i) {
        int row = r0 + wm * 32 + i * 16 + g;
#pragma unroll
        for (int j = 0; j < 8; ++j) {
            int col = c0 + wn * 64 + j * 8 + 2 * q;
#pragma unroll
            for (int hrow = 0; hrow < 2; ++hrow) {
                float v0 = c[i][j][hrow * 2], v1 = c[i][j][hrow * 2 + 1];
                bf16 h0, l0, h1, l1;
                split_bf16(v0, h0, l0); split_bf16(v1, h1, l1);
                size_t off = (size_t)(row + hrow * 8) * ZC + col;
                *(uint32_t*)&g_Zh[off] = pack2(h0, h1);
                *(uint32_t*)&g_Zl[off] = pack2(l0, l1);
            }
        }
    }
}

// ---------------- stage2 (HMMA): mid = sum_k M'_k * Z[:,64k:64k+64] --------------
// CTA 128n x 64o per batch; K = 3 parts * 4 ksup * 512m; BK=32
#define S2_APAD 40
#define S2_BPAD 72
#define S2_NCHUNK 192

__global__ __launch_bounds__(256) void stage2_mma() {
    __shared__ __align__(16) bf16 As_[2][128 * S2_APAD];
    __shared__ __align__(16) bf16 Bs_[2][32 * S2_BPAD];

    const int tid = threadIdx.x;
    const int warp = tid >> 5, lane = tid & 31;
    const int wm = warp >> 1, wn = warp & 1;
    const int g = lane >> 2, q = lane & 3;
    const int n0 = blockIdx.x * 128;
    const int b  = blockIdx.y;

    const int aLdRow = tid >> 2, aLdSeg = tid & 3;   // A: 128x32
    const int bLdRow = tid >> 3, bLdSeg = tid & 7;   // B: 32x64
    const int fragRow  = lane & 15;
    const int fragCol8 = (lane >> 4) * 8;

    uint32_t aBase[2] = { smem_u32(&As_[0][0]), smem_u32(&As_[1][0]) };
    uint32_t bBase[2] = { smem_u32(&Bs_[0][0]), smem_u32(&Bs_[1][0]) };

    float c[2][4][4];
#pragma unroll
    for (int i = 0; i < 2; ++i)
#pragma unroll
        for (int j = 0; j < 4; ++j)
#pragma unroll
            for (int t = 0; t < 4; ++t) c[i][j][t] = 0.f;

    uint4 pa[2], pb;
    auto ldg = [&](int ch) {
        int part = ch >> 6;          // 0,1,2
        int rem = ch & 63;
        int k = rem >> 4;            // 0..3
        int mpos = (rem & 15) * 32;
        const bf16* Am;
        if (part == 1) Am = (k & 1) ? g_M2l : g_Ml;
        else           Am = (k & 1) ? g_M2h : g_Mh;
        Am += (size_t)(k >> 1) * AS;
        pa[0] = *(const uint4*)(Am + (size_t)(n0 + aLdRow) * NN + mpos + aLdSeg * 8);
        pa[1] = *(const uint4*)(Am + (size_t)(n0 + aLdRow + 64) * NN + mpos + aLdSeg * 8);
        const bf16* Zp = (part == 2) ? g_Zl : g_Zh;
        pb = *(const uint4*)(Zp + (size_t)(b * NN + mpos + bLdRow) * ZC + k * 64 + bLdSeg * 8);
    };
    auto sts = [&](int buf) {
        *(uint4*)(&As_[buf][aLdRow * S2_APAD + aLdSeg * 8]) = pa[0];
        *(uint4*)(&As_[buf][(aLdRow + 64) * S2_APAD + aLdSeg * 8]) = pa[1];
        *(uint4*)(&Bs_[buf][bLdRow * S2_BPAD + bLdSeg * 8]) = pb;
    };

    ldg(0); sts(0);
    __syncthreads();

    for (int ch = 0; ch < S2_NCHUNK; ++ch) {
        int buf = ch & 1;
        if (ch + 1 < S2_NCHUNK) ldg(ch + 1);
#pragma unroll
        for (int ks = 0; ks < 32; ks += 16) {
            uint32_t a[2][4];
#pragma unroll
            for (int i = 0; i < 2; ++i) {
                uint32_t addr = aBase[buf]
                    + (uint32_t)(wm * 32 + i * 16 + fragRow) * (S2_APAD * 2)
                    + (uint32_t)(ks + fragCol8) * 2;
                LDSM_X4(a[i][0], a[i][1], a[i][2], a[i][3], addr);
            }
            uint32_t b_[4][2];
#pragma unroll
            for (int jj = 0; jj < 2; ++jj) {
                uint32_t addr = bBase[buf]
                    + (uint32_t)(ks + fragRow) * (S2_BPAD * 2)
                    + (uint32_t)(wn * 32 + jj * 16 + fragCol8) * 2;
                uint32_t r0_, r1_, r2_, r3_;
                LDSM_X4T(r0_, r1_, r2_, r3_, addr);
                b_[2*jj][0] = r0_;   b_[2*jj][1] = r1_;
                b_[2*jj+1][0] = r2_; b_[2*jj+1][1] = r3_;
            }
#pragma unroll
            for (int i = 0; i < 2; ++i)
#pragma unroll
                for (int j = 0; j < 4; ++j)
                    MMA_BF16(c[i][j][0], c[i][j][1], c[i][j][2], c[i][j][3],
                             a[i][0], a[i][1], a[i][2], a[i][3], b_[j][0], b_[j][1]);
        }
        if (ch + 1 < S2_NCHUNK) sts((ch + 1) & 1);
        __syncthreads();
    }

    // epilogue: fp32 -> g_mid
#pragma unroll
    for (int i = 0; i < 2; ++i) {
        int row = n0 + wm * 32 + i * 16 + g;
#pragma unroll
        for (int j = 0; j < 4; ++j) {
            int col = wn * 32 + j * 8 + 2 * q;
            float2 v0 = { c[i][j][0], c[i][j][1] };
            float2 v1 = { c[i][j][2], c[i][j][3] };
            *(float2*)&g_mid[(size_t)(b * NN + row) * OUTC + col] = v0;
            *(float2*)&g_mid[(size_t)(b * NN + row + 8) * OUTC + col] = v1;
        }
    }
}

// ---------------- BN tail (unchanged, passing) ----------------
__global__ void zero_stats() {
    if (threadIdx.x < OUTC) { g_sum[threadIdx.x] = 0.f; g_sumsq[threadIdx.x] = 0.f; }
}
__global__ __launch_bounds__(256) void bn_stats() {
    const int c = threadIdx.x & 63;
    const int rl = threadIdx.x >> 6;
    float s = 0.f, s2 = 0.f;
    for (int r = blockIdx.x * 4 + rl; r < ROWS; r += gridDim.x * 4) {
        float v = g_mid[(size_t)r * OUTC + c];
        s += v; s2 += v * v;
    }
    __shared__ float sh[256], sh2[256];
    sh[threadIdx.x] = s; sh2[threadIdx.x] = s2;
    __syncthreads();
    if (rl == 0) {
        s  = sh[c] + sh[c + 64] + sh[c + 128] + sh[c + 192];
        s2 = sh2[c] + sh2[c + 64] + sh2[c + 128] + sh2[c + 192];
        atomicAdd(&g_sum[c], s); atomicAdd(&g_sumsq[c], s2);
    }
}
__global__ __launch_bounds__(256) void bn_relu_fc(
    const float* __restrict__ gamma, const float* __restrict__ beta,
    const float* __restrict__ w2,    const float* __restrict__ b2,
    float* __restrict__ out)
{
    __shared__ float w2t[64][65];
    __shared__ float scale_s[64], shift_s[64];
    __shared__ float y[4][64];
    const int tid = threadIdx.x;
#pragma unroll
    for (int t = 0; t < 16; ++t) {
        int idx = tid + t * 256;
        int o = idx >> 6, c = idx & 63;
        w2t[c][o] = w2[idx];
    }
    if (tid < OUTC) {
        const float invN = 1.0f / (float)ROWS;
        float mean = g_sum[tid] * invN;
        float var  = g_sumsq[tid] * invN - mean * mean;
        float sc   = gamma[tid] * rsqrtf(var + 1e-5f);
        scale_s[tid] = sc;
        shift_s[tid] = beta[tid] - mean * sc;
    }
    __syncthreads();
    const int rl = tid >> 6, c = tid & 63;
    for (int r0 = blockIdx.x * 4; r0 < ROWS; r0 += gridDim.x * 4) {
        int r = r0 + rl;
        float v = g_mid[(size_t)r * OUTC + c];
        v = fmaxf(fmaf(v, scale_s[c], shift_s[c]), 0.f);
        y[rl][c] = v;
        __syncthreads();
        float acc = b2[c];
#pragma unroll
        for (int cc = 0; cc < 64; ++cc)
            acc = fmaf(y[rl][cc], w2t[cc][c], acc);
        out[(size_t)r * OUTC + c] = acc;
        __syncthreads();
    }
}

// ---------------- launch ----------------
extern "C" void kernel_launch(void* const* d_in, const int* in_sizes, int n_in,
                              void* d_out, int out_size) {
    const float* x       = (const float*)d_in[0];
    const float* support = (const float*)d_in[1];
    const float* weight  = (const float*)d_in[2];
    const float* eps     = (const float*)d_in[3];
    const float* gamma   = (const float*)d_in[4];
    const float* beta    = (const float*)d_in[5];
    const float* w2      = (const float*)d_in[6];
    const float* b2      = (const float*)d_in[7];
    float* out           = (float*)d_out;

    prep_M<<<(2 * (int)AS + 255) / 256, 256>>>(support, eps);
    prep_W<<<(ZC * BD + 255) / 256, 256>>>(weight);
    split_X<<<(int)(ROWS * (size_t)BD / 4 + 255) / 256, 256>>>(x);

    gemm_m2_mma<<<dim3(NN / 64, NN / 128, 2), 256>>>();

    stage1_mma<<<dim3(ZC / 128, ROWS / 128), 256>>>();

    stage2_mma<<<dim3(NN / 128, BB), 256>>>();

    zero_stats<<<1, 64>>>();
    bn_stats<<<128, 256>>>();
    bn_relu_fc<<<512, 256>>>(gamma, beta, w2, b2, out);
}

// round 8
// speedup vs baseline: 11.8873x; 1.2651x over previous
#include <cuda_runtime.h>
#include <cuda_bf16.h>
#include <math.h>
#include <stdint.h>

typedef __nv_bfloat16 bf16;

// ---------------- problem dims ----------------
#define BB    32
#define NN    512
#define BD    768            // L*H
#define ROWS  (BB*NN)        // 16384
#define OUTC  64
#define KSUP  4
#define ZC    256            // KSUP*OUTC
#define AS    ((size_t)NN*NN)   // 262144 = 2^18

// ---------------- device scratch (no allocation) ----------------
__device__ __align__(256) bf16  g_Mh [2*AS], g_Ml [2*AS];    // M = A+(1+eps)I, split
__device__ __align__(256) bf16  g_M2h[2*AS], g_M2l[2*AS];    // M^2, split
__device__ __align__(256) float g_M2p[6*AS];                 // M^2 per-part fp32 slabs
__device__ __align__(256) bf16  g_Xh[(size_t)ROWS*BD], g_Xl[(size_t)ROWS*BD];
__device__ __align__(256) bf16  g_Wth[ZC*BD], g_Wtl[ZC*BD];  // W^T repack [ko][d]
__device__ __align__(256) bf16  g_Zh[(size_t)ROWS*ZC], g_Zl[(size_t)ROWS*ZC];
__device__ __align__(256) float g_mid[(size_t)ROWS*OUTC];
__device__ float g_sum[OUTC], g_sumsq[OUTC];

__device__ __forceinline__ uint32_t smem_u32(const void* p) {
    uint32_t a;
    asm("{ .reg .u64 t; cvta.to.shared.u64 t, %1; cvt.u32.u64 %0, t; }" : "=r"(a) : "l"(p));
    return a;
}
__device__ __forceinline__ void split_bf16(float v, bf16& h, bf16& l) {
    h = __float2bfloat16(v);
    l = __float2bfloat16(v - __bfloat162float(h));
}
__device__ __forceinline__ uint32_t pack2(bf16 lo, bf16 hi) {
    return ((uint32_t)__bfloat16_as_ushort(hi) << 16) | __bfloat16_as_ushort(lo);
}
__device__ __forceinline__ void cp16(uint32_t s, const void* g) {
    asm volatile("cp.async.cg.shared.global [%0], [%1], 16;"
                 :: "r"(s), "l"(__cvta_generic_to_global(g)) : "memory");
}
#define CP_COMMIT() asm volatile("cp.async.commit_group;" ::: "memory")
#define CP_WAIT2()  asm volatile("cp.async.wait_group 2;"  ::: "memory")

#define LDSM_X4(r0,r1,r2,r3,addr) \
    asm volatile("ldmatrix.sync.aligned.m8n8.x4.shared.b16 {%0,%1,%2,%3}, [%4];" \
                 : "=r"(r0), "=r"(r1), "=r"(r2), "=r"(r3) : "r"(addr))
#define LDSM_X4T(r0,r1,r2,r3,addr) \
    asm volatile("ldmatrix.sync.aligned.m8n8.x4.trans.shared.b16 {%0,%1,%2,%3}, [%4];" \
                 : "=r"(r0), "=r"(r1), "=r"(r2), "=r"(r3) : "r"(addr))
#define MMA_BF16(c0,c1,c2,c3,a0,a1,a2,a3,b0,b1) \
    asm volatile("mma.sync.aligned.m16n8k16.row.col.f32.bf16.bf16.f32 " \
                 "{%0,%1,%2,%3}, {%4,%5,%6,%7}, {%8,%9}, {%0,%1,%2,%3};" \
                 : "+f"(c0), "+f"(c1), "+f"(c2), "+f"(c3) \
                 : "r"(a0), "r"(a1), "r"(a2), "r"(a3), "r"(b0), "r"(b1))

// ---------------- prep kernels ----------------
__global__ void prep_M(const float* __restrict__ sup, const float* __restrict__ eps) {
    int idx = blockIdx.x * blockDim.x + threadIdx.x;
    if (idx >= 2 * (int)AS) return;
    int rest = idx & (int)(AS - 1);
    int n = rest >> 9, m = rest & 511;
    float v = sup[idx] + ((n == m) ? (1.0f + eps[0]) : 0.0f);
    bf16 h, l; split_bf16(v, h, l);
    g_Mh[idx] = h; g_Ml[idx] = l;
}

__global__ void prep_W(const float* __restrict__ w) {
    int idx = blockIdx.x * blockDim.x + threadIdx.x;   // ko*768 + d
    if (idx >= ZC * BD) return;
    int d  = idx % BD;
    int ko = idx / BD;
    int k = ko >> 6, o = ko & 63;
    int l = d >> 6, h = d & 63;
    float v = w[((size_t)l * 256 + h * 4 + k) * OUTC + o];
    bf16 hh, ll; split_bf16(v, hh, ll);
    g_Wth[idx] = hh; g_Wtl[idx] = ll;
}

__global__ void split_X(const float* __restrict__ x) {
    int idx = blockIdx.x * blockDim.x + threadIdx.x;
    if (idx >= (int)(ROWS * (size_t)BD / 4)) return;
    float4 v = ((const float4*)x)[idx];
    bf16 h0,l0,h1,l1,h2,l2,h3,l3;
    split_bf16(v.x,h0,l0); split_bf16(v.y,h1,l1);
    split_bf16(v.z,h2,l2); split_bf16(v.w,h3,l3);
    uint2 ph, pl;
    ph.x = pack2(h0,h1); ph.y = pack2(h2,h3);
    pl.x = pack2(l0,l1); pl.y = pack2(l2,l3);
    ((uint2*)g_Xh)[idx] = ph;
    ((uint2*)g_Xl)[idx] = pl;
}

// ---------------- M^2 (HMMA, split-K over 3 parts): per-part fp32 slab ----------
// grid (NN/64, NN/128, 6); z: part = z>>1, s = z&1. CTA 128n x 64m, 16 chunks.
#define M2_APAD 40
#define M2_BPAD 72
#define M2_NCHUNK 16

__global__ __launch_bounds__(256) void gemm_m2_mma() {
    __shared__ __align__(16) bf16 As_[2][128 * M2_APAD];
    __shared__ __align__(16) bf16 Bs_[2][32 * M2_BPAD];

    const int tid = threadIdx.x;
    const int warp = tid >> 5, lane = tid & 31;
    const int wm = warp >> 1, wn = warp & 1;
    const int g = lane >> 2, q = lane & 3;
    const int part = blockIdx.z >> 1;
    const int s    = blockIdx.z & 1;
    const int n0 = blockIdx.y * 128;
    const int m0 = blockIdx.x * 64;

    const int aLdRow = tid >> 2, aLdSeg = tid & 3;
    const int bLdRow = tid >> 3, bLdSeg = tid & 7;
    const int fragRow  = lane & 15;
    const int fragCol8 = (lane >> 4) * 8;

    uint32_t aBase[2] = { smem_u32(&As_[0][0]), smem_u32(&As_[1][0]) };
    uint32_t bBase[2] = { smem_u32(&Bs_[0][0]), smem_u32(&Bs_[1][0]) };

    const bf16* Ap = ((part == 1) ? g_Ml : g_Mh) + (size_t)s * AS;
    const bf16* Bp = ((part == 2) ? g_Ml : g_Mh) + (size_t)s * AS;

    float c[2][4][4];
#pragma unroll
    for (int i = 0; i < 2; ++i)
#pragma unroll
        for (int j = 0; j < 4; ++j)
#pragma unroll
            for (int t = 0; t < 4; ++t) c[i][j][t] = 0.f;

    uint4 pa[2], pb;
    auto ldg = [&](int ch) {
        int jpos = ch * 32;
        pa[0] = *(const uint4*)(Ap + (size_t)(n0 + aLdRow) * NN + jpos + aLdSeg * 8);
        pa[1] = *(const uint4*)(Ap + (size_t)(n0 + aLdRow + 64) * NN + jpos + aLdSeg * 8);
        pb    = *(const uint4*)(Bp + (size_t)(jpos + bLdRow) * NN + m0 + bLdSeg * 8);
    };
    auto sts = [&](int buf) {
        *(uint4*)(&As_[buf][aLdRow * M2_APAD + aLdSeg * 8]) = pa[0];
        *(uint4*)(&As_[buf][(aLdRow + 64) * M2_APAD + aLdSeg * 8]) = pa[1];
        *(uint4*)(&Bs_[buf][bLdRow * M2_BPAD + bLdSeg * 8]) = pb;
    };

    ldg(0); sts(0);
    __syncthreads();

    for (int ch = 0; ch < M2_NCHUNK; ++ch) {
        int buf = ch & 1;
        if (ch + 1 < M2_NCHUNK) ldg(ch + 1);
#pragma unroll
        for (int ks = 0; ks < 32; ks += 16) {
            uint32_t a[2][4];
#pragma unroll
            for (int i = 0; i < 2; ++i) {
                uint32_t addr = aBase[buf]
                    + (uint32_t)(wm * 32 + i * 16 + fragRow) * (M2_APAD * 2)
                    + (uint32_t)(ks + fragCol8) * 2;
                LDSM_X4(a[i][0], a[i][1], a[i][2], a[i][3], addr);
            }
            uint32_t b[4][2];
#pragma unroll
            for (int jj = 0; jj < 2; ++jj) {
                uint32_t addr = bBase[buf]
                    + (uint32_t)(ks + fragRow) * (M2_BPAD * 2)
                    + (uint32_t)(wn * 32 + jj * 16 + fragCol8) * 2;
                uint32_t r0_, r1_, r2_, r3_;
                LDSM_X4T(r0_, r1_, r2_, r3_, addr);
                b[2*jj][0] = r0_;   b[2*jj][1] = r1_;
                b[2*jj+1][0] = r2_; b[2*jj+1][1] = r3_;
            }
#pragma unroll
            for (int i = 0; i < 2; ++i)
#pragma unroll
                for (int j = 0; j < 4; ++j)
                    MMA_BF16(c[i][j][0], c[i][j][1], c[i][j][2], c[i][j][3],
                             a[i][0], a[i][1], a[i][2], a[i][3], b[j][0], b[j][1]);
        }
        if (ch + 1 < M2_NCHUNK) sts((ch + 1) & 1);
        __syncthreads();
    }

    float* O = g_M2p + (size_t)(part * 2 + s) * AS;
#pragma unroll
    for (int i = 0; i < 2; ++i) {
        int row = n0 + wm * 32 + i * 16 + g;
#pragma unroll
        for (int j = 0; j < 4; ++j) {
            int col = m0 + wn * 32 + j * 8 + 2 * q;
            float2 v0 = { c[i][j][0], c[i][j][1] };
            float2 v1 = { c[i][j][2], c[i][j][3] };
            *(float2*)&O[(size_t)row * NN + col] = v0;
            *(float2*)&O[(size_t)(row + 8) * NN + col] = v1;
        }
    }
}

// combine 3 part-slabs (fixed order, deterministic) -> split bf16
__global__ void m2_combine() {
    int idx = blockIdx.x * blockDim.x + threadIdx.x;
    if (idx >= 2 * (int)AS) return;
    int s = idx >> 18;
    size_t rest = (size_t)(idx & (int)(AS - 1));
    float v = g_M2p[(size_t)(0 + s) * AS + rest]
            + g_M2p[(size_t)(2 + s) * AS + rest]
            + g_M2p[(size_t)(4 + s) * AS + rest];
    bf16 h, l; split_bf16(v, h, l);
    g_M2h[idx] = h; g_M2l[idx] = l;
}

// ---------------- stage1 (HMMA, 4-stage cp.async): Z = XhWh + XlWh + XhWl --------
#define S1_PAD 40
#define S1_NCHUNK 72          // 3 parts * 768/32
#define S1_TILE (128 * S1_PAD)
#define S1_SMEM (8 * S1_TILE * 2)   // 4 A stages + 4 B stages, bytes

__global__ __launch_bounds__(256) void stage1_mma() {
    extern __shared__ __align__(16) bf16 sm1[];
    bf16* Asm = sm1;                  // [4][S1_TILE]
    bf16* Bsm = sm1 + 4 * S1_TILE;    // [4][S1_TILE]

    const int tid = threadIdx.x;
    const int warp = tid >> 5, lane = tid & 31;
    const int wm = warp >> 1, wn = warp & 1;
    const int g = lane >> 2, q = lane & 3;
    const int r0 = blockIdx.y * 128;
    const int c0 = blockIdx.x * 128;

    const int ldrow = tid >> 2;
    const int ldseg = tid & 3;

    // round-5 validated lane-invariant ldmatrix offsets
    const int aRowOff = ((lane >> 3) & 1) * 8 + (lane & 7);
    const int aKOff   = (lane >> 4) * 8;
    const int bRowOff = (lane >> 4) * 8 + (lane & 7);
    const int bKOff   = ((lane >> 3) & 1) * 8;

    uint32_t aB[4], bB[4];
#pragma unroll
    for (int st = 0; st < 4; ++st) {
        aB[st] = smem_u32(Asm + st * S1_TILE);
        bB[st] = smem_u32(Bsm + st * S1_TILE);
    }

    float c[2][8][4];
#pragma unroll
    for (int i = 0; i < 2; ++i)
#pragma unroll
        for (int j = 0; j < 8; ++j)
#pragma unroll
            for (int t = 0; t < 4; ++t) c[i][j][t] = 0.f;

    auto load_stage = [&](int ch) {
        int st = ch & 3;
        int part = ch / 24;
        int kpos = (ch % 24) * 32;
        const bf16* Ap = (part == 1) ? g_Xl : g_Xh;
        const bf16* Bp = (part == 2) ? g_Wtl : g_Wth;
#pragma unroll
        for (int t = 0; t < 2; ++t) {
            int row = ldrow + t * 64;
            uint32_t so = (uint32_t)(row * S1_PAD + ldseg * 8) * 2;
            cp16(aB[st] + so, Ap + (size_t)(r0 + row) * BD + kpos + ldseg * 8);
            cp16(bB[st] + so, Bp + (size_t)(c0 + row) * BD + kpos + ldseg * 8);
        }
        CP_COMMIT();
    };

    load_stage(0); load_stage(1); load_stage(2);

    for (int ch = 0; ch < S1_NCHUNK; ++ch) {
        CP_WAIT2();
        __syncthreads();
        int st = ch & 3;
#pragma unroll
        for (int ks = 0; ks < 32; ks += 16) {
            uint32_t a[2][4];
#pragma unroll
            for (int i = 0; i < 2; ++i) {
                uint32_t addr = aB[st]
                    + (uint32_t)(wm * 32 + i * 16 + aRowOff) * (S1_PAD * 2)
                    + (uint32_t)(ks + aKOff) * 2;
                LDSM_X4(a[i][0], a[i][1], a[i][2], a[i][3], addr);
            }
            uint32_t b[8][2];
#pragma unroll
            for (int j2 = 0; j2 < 4; ++j2) {
                uint32_t addr = bB[st]
                    + (uint32_t)(wn * 64 + j2 * 16 + bRowOff) * (S1_PAD * 2)
                    + (uint32_t)(ks + bKOff) * 2;
                uint32_t r0_, r1_, r2_, r3_;
                LDSM_X4(r0_, r1_, r2_, r3_, addr);
                b[2*j2][0]   = r0_; b[2*j2][1]   = r1_;
                b[2*j2+1][0] = r2_; b[2*j2+1][1] = r3_;
            }
#pragma unroll
            for (int i = 0; i < 2; ++i)
#pragma unroll
                for (int j = 0; j < 8; ++j)
                    MMA_BF16(c[i][j][0], c[i][j][1], c[i][j][2], c[i][j][3],
                             a[i][0], a[i][1], a[i][2], a[i][3], b[j][0], b[j][1]);
        }
        if (ch + 3 < S1_NCHUNK) load_stage(ch + 3);
        else CP_COMMIT();   // empty group keeps wait(2) arithmetic exact at tail
    }

    // epilogue: split fp32 -> Zh/Zl bf16
#pragma unroll
    for (int i = 0; i < 2; ++i) {
        int row = r0 + wm * 32 + i * 16 + g;
#pragma unroll
        for (int j = 0; j < 8; ++j) {
            int col = c0 + wn * 64 + j * 8 + 2 * q;
#pragma unroll
            for (int hrow = 0; hrow < 2; ++hrow) {
                float v0 = c[i][j][hrow * 2], v1 = c[i][j][hrow * 2 + 1];
                bf16 h0, l0, h1, l1;
                split_bf16(v0, h0, l0); split_bf16(v1, h1, l1);
                size_t off = (size_t)(row + hrow * 8) * ZC + col;
                *(uint32_t*)&g_Zh[off] = pack2(h0, h1);
                *(uint32_t*)&g_Zl[off] = pack2(l0, l1);
            }
        }
    }
}

// ---------------- stage2 (HMMA, 4-stage cp.async): mid = sum_k M'_k Z_k ----------
#define S2_APAD 40
#define S2_BPAD 72
#define S2_NCHUNK 192
#define S2_ATILE (128 * S2_APAD)
#define S2_BTILE (32 * S2_BPAD)
#define S2_SMEM ((4 * S2_ATILE + 4 * S2_BTILE) * 2)

__global__ __launch_bounds__(256) void stage2_mma() {
    extern __shared__ __align__(16) bf16 sm2[];
    bf16* Asm = sm2;
    bf16* Bsm = sm2 + 4 * S2_ATILE;

    const int tid = threadIdx.x;
    const int warp = tid >> 5, lane = tid & 31;
    const int wm = warp >> 1, wn = warp & 1;
    const int g = lane >> 2, q = lane & 3;
    const int n0 = blockIdx.x * 128;
    const int b  = blockIdx.y;

    const int aLdRow = tid >> 2, aLdSeg = tid & 3;
    const int bLdRow = tid >> 3, bLdSeg = tid & 7;
    const int fragRow  = lane & 15;
    const int fragCol8 = (lane >> 4) * 8;

    uint32_t aB[4], bB[4];
#pragma unroll
    for (int st = 0; st < 4; ++st) {
        aB[st] = smem_u32(Asm + st * S2_ATILE);
        bB[st] = smem_u32(Bsm + st * S2_BTILE);
    }

    float c[2][4][4];
#pragma unroll
    for (int i = 0; i < 2; ++i)
#pragma unroll
        for (int j = 0; j < 4; ++j)
#pragma unroll
            for (int t = 0; t < 4; ++t) c[i][j][t] = 0.f;

    auto load_stage = [&](int ch) {
        int st = ch & 3;
        int part = ch >> 6;          // 0,1,2
        int rem = ch & 63;
        int k = rem >> 4;            // 0..3
        int mpos = (rem & 15) * 32;
        const bf16* Am;
        if (part == 1) Am = (k & 1) ? g_M2l : g_Ml;
        else           Am = (k & 1) ? g_M2h : g_Mh;
        Am += (size_t)(k >> 1) * AS;
        cp16(aB[st] + (uint32_t)(aLdRow * S2_APAD + aLdSeg * 8) * 2,
             Am + (size_t)(n0 + aLdRow) * NN + mpos + aLdSeg * 8);
        cp16(aB[st] + (uint32_t)((aLdRow + 64) * S2_APAD + aLdSeg * 8) * 2,
             Am + (size_t)(n0 + aLdRow + 64) * NN + mpos + aLdSeg * 8);
        const bf16* Zp = (part == 2) ? g_Zl : g_Zh;
        cp16(bB[st] + (uint32_t)(bLdRow * S2_BPAD + bLdSeg * 8) * 2,
             Zp + (size_t)(b * NN + mpos + bLdRow) * ZC + k * 64 + bLdSeg * 8);
        CP_COMMIT();
    };

    load_stage(0); load_stage(1); load_stage(2);

    for (int ch = 0; ch < S2_NCHUNK; ++ch) {
        CP_WAIT2();
        __syncthreads();
        int st = ch & 3;
#pragma unroll
        for (int ks = 0; ks < 32; ks += 16) {
            uint32_t a[2][4];
#pragma unroll
            for (int i = 0; i < 2; ++i) {
                uint32_t addr = aB[st]
                    + (uint32_t)(wm * 32 + i * 16 + fragRow) * (S2_APAD * 2)
                    + (uint32_t)(ks + fragCol8) * 2;
                LDSM_X4(a[i][0], a[i][1], a[i][2], a[i][3], addr);
            }
            uint32_t b_[4][2];
#pragma unroll
            for (int jj = 0; jj < 2; ++jj) {
                uint32_t addr = bB[st]
                    + (uint32_t)(ks + fragRow) * (S2_BPAD * 2)
                    + (uint32_t)(wn * 32 + jj * 16 + fragCol8) * 2;
                uint32_t r0_, r1_, r2_, r3_;
                LDSM_X4T(r0_, r1_, r2_, r3_, addr);
                b_[2*jj][0] = r0_;   b_[2*jj][1] = r1_;
                b_[2*jj+1][0] = r2_; b_[2*jj+1][1] = r3_;
            }
#pragma unroll
            for (int i = 0; i < 2; ++i)
#pragma unroll
                for (int j = 0; j < 4; ++j)
                    MMA_BF16(c[i][j][0], c[i][j][1], c[i][j][2], c[i][j][3],
                             a[i][0], a[i][1], a[i][2], a[i][3], b_[j][0], b_[j][1]);
        }
        if (ch + 3 < S2_NCHUNK) load_stage(ch + 3);
        else CP_COMMIT();
    }

    // epilogue: fp32 -> g_mid
#pragma unroll
    for (int i = 0; i < 2; ++i) {
        int row = n0 + wm * 32 + i * 16 + g;
#pragma unroll
        for (int j = 0; j < 4; ++j) {
            int col = wn * 32 + j * 8 + 2 * q;
            float2 v0 = { c[i][j][0], c[i][j][1] };
            float2 v1 = { c[i][j][2], c[i][j][3] };
            *(float2*)&g_mid[(size_t)(b * NN + row) * OUTC + col] = v0;
            *(float2*)&g_mid[(size_t)(b * NN + row + 8) * OUTC + col] = v1;
        }
    }
}

// ---------------- BN tail ----------------
__global__ void zero_stats() {
    if (threadIdx.x < OUTC) { g_sum[threadIdx.x] = 0.f; g_sumsq[threadIdx.x] = 0.f; }
}
__global__ __launch_bounds__(256) void bn_stats() {
    const int c = threadIdx.x & 63;
    const int rl = threadIdx.x >> 6;
    float s = 0.f, s2 = 0.f;
    for (int r = blockIdx.x * 4 + rl; r < ROWS; r += gridDim.x * 4) {
        float v = g_mid[(size_t)r * OUTC + c];
        s += v; s2 += v * v;
    }
    __shared__ float sh[256], sh2[256];
    sh[threadIdx.x] = s; sh2[threadIdx.x] = s2;
    __syncthreads();
    if (rl == 0) {
        s  = sh[c] + sh[c + 64] + sh[c + 128] + sh[c + 192];
        s2 = sh2[c] + sh2[c + 64] + sh2[c + 128] + sh2[c + 192];
        atomicAdd(&g_sum[c], s); atomicAdd(&g_sumsq[c], s2);
    }
}
// tiled BN+ReLU+FC: 64 rows/block, one sync between phases
__global__ __launch_bounds__(256) void bn_relu_fc2(
    const float* __restrict__ gamma, const float* __restrict__ beta,
    const float* __restrict__ w2,    const float* __restrict__ b2,
    float* __restrict__ out)
{
    __shared__ float w2t[64][65];    // w2t[c][o] = w2[o][c]
    __shared__ float ysm[64][65];
    __shared__ float scale_s[64], shift_s[64];
    const int tid = threadIdx.x;
    const int r0 = blockIdx.x * 64;

#pragma unroll
    for (int t = 0; t < 16; ++t) {
        int idx = tid + t * 256;
        int o = idx >> 6, cc = idx & 63;
        w2t[cc][o] = w2[idx];
    }
    if (tid < OUTC) {
        const float invN = 1.0f / (float)ROWS;
        float mean = g_sum[tid] * invN;
        float var  = g_sumsq[tid] * invN - mean * mean;
        float sc   = gamma[tid] * rsqrtf(var + 1e-5f);
        scale_s[tid] = sc;
        shift_s[tid] = beta[tid] - mean * sc;
    }
    __syncthreads();

#pragma unroll
    for (int t = 0; t < 16; ++t) {
        int idx = tid + t * 256;
        int r = idx >> 6, cc = idx & 63;
        float v = g_mid[(size_t)(r0 + r) * OUTC + cc];
        ysm[r][cc] = fmaxf(fmaf(v, scale_s[cc], shift_s[cc]), 0.f);
    }
    __syncthreads();

    const int tr = tid >> 4, tc = tid & 15;    // rows tr*4.., cols tc*4..
    float acc[4][4];
#pragma unroll
    for (int i = 0; i < 4; ++i)
#pragma unroll
        for (int j = 0; j < 4; ++j) acc[i][j] = b2[tc * 4 + j];
    for (int k = 0; k < 64; ++k) {
        float w0 = w2t[k][tc * 4 + 0], w1 = w2t[k][tc * 4 + 1];
        float w2v = w2t[k][tc * 4 + 2], w3 = w2t[k][tc * 4 + 3];
#pragma unroll
        for (int i = 0; i < 4; ++i) {
            float y = ysm[tr * 4 + i][k];
            acc[i][0] = fmaf(y, w0, acc[i][0]);
            acc[i][1] = fmaf(y, w1, acc[i][1]);
            acc[i][2] = fmaf(y, w2v, acc[i][2]);
            acc[i][3] = fmaf(y, w3, acc[i][3]);
        }
    }
#pragma unroll
    for (int i = 0; i < 4; ++i)
        *(float4*)&out[(size_t)(r0 + tr * 4 + i) * OUTC + tc * 4] = *(float4*)&acc[i][0];
}

// ---------------- launch ----------------
extern "C" void kernel_launch(void* const* d_in, const int* in_sizes, int n_in,
                              void* d_out, int out_size) {
    const float* x       = (const float*)d_in[0];
    const float* support = (const float*)d_in[1];
    const float* weight  = (const float*)d_in[2];
    const float* eps     = (const float*)d_in[3];
    const float* gamma   = (const float*)d_in[4];
    const float* beta    = (const float*)d_in[5];
    const float* w2      = (const float*)d_in[6];
    const float* b2      = (const float*)d_in[7];
    float* out           = (float*)d_out;

    cudaFuncSetAttribute(stage1_mma, cudaFuncAttributeMaxDynamicSharedMemorySize, S1_SMEM);
    cudaFuncSetAttribute(stage2_mma, cudaFuncAttributeMaxDynamicSharedMemorySize, S2_SMEM);

    prep_M<<<(2 * (int)AS + 255) / 256, 256>>>(support, eps);
    prep_W<<<(ZC * BD + 255) / 256, 256>>>(weight);
    split_X<<<(int)(ROWS * (size_t)BD / 4 + 255) / 256, 256>>>(x);

    gemm_m2_mma<<<dim3(NN / 64, NN / 128, 6), 256>>>();
    m2_combine<<<(2 * (int)AS + 255) / 256, 256>>>();

    stage1_mma<<<dim3(ZC / 128, ROWS / 128), 256, S1_SMEM>>>();

    stage2_mma<<<dim3(NN / 128, BB), 256, S2_SMEM>>>();

    zero_stats<<<1, 64>>>();
    bn_stats<<<128, 256>>>();
    bn_relu_fc2<<<ROWS / 64, 256>>>(gamma, beta, w2, b2, out);
}

// round 9
// speedup vs baseline: 13.2315x; 1.1131x over previous
#include <cuda_runtime.h>
#include <cuda_bf16.h>
#include <math.h>
#include <stdint.h>

typedef __nv_bfloat16 bf16;

// ---------------- problem dims ----------------
#define BB    32
#define NN    512
#define BD    768            // L*H
#define ROWS  (BB*NN)        // 16384
#define OUTC  64
#define KSUP  4
#define ZC    256            // KSUP*OUTC
#define AS    ((size_t)NN*NN)   // 262144 = 2^18

// ---------------- device scratch (no allocation) ----------------
__device__ __align__(256) bf16  g_Mh [2*AS], g_Ml [2*AS];    // M = A+(1+eps)I, split
__device__ __align__(256) bf16  g_M2h[2*AS], g_M2l[2*AS];    // M^2, split
__device__ __align__(256) float g_M2p[6*AS];                 // M^2 per-part fp32 slabs
__device__ __align__(256) bf16  g_Xh[(size_t)ROWS*BD], g_Xl[(size_t)ROWS*BD];
__device__ __align__(256) bf16  g_Wth[ZC*BD], g_Wtl[ZC*BD];  // W^T repack [ko][d]
__device__ __align__(256) bf16  g_Zh[(size_t)ROWS*ZC], g_Zl[(size_t)ROWS*ZC];
__device__ __align__(256) float g_midp[2][(size_t)ROWS*OUTC]; // stage2 split-K slabs
__device__ __align__(256) float g_mid[(size_t)ROWS*OUTC];
__device__ float g_sum[OUTC], g_sumsq[OUTC];

__device__ __forceinline__ uint32_t smem_u32(const void* p) {
    uint32_t a;
    asm("{ .reg .u64 t; cvta.to.shared.u64 t, %1; cvt.u32.u64 %0, t; }" : "=r"(a) : "l"(p));
    return a;
}
__device__ __forceinline__ void split_bf16(float v, bf16& h, bf16& l) {
    h = __float2bfloat16(v);
    l = __float2bfloat16(v - __bfloat162float(h));
}
__device__ __forceinline__ uint32_t pack2(bf16 lo, bf16 hi) {
    return ((uint32_t)__bfloat16_as_ushort(hi) << 16) | __bfloat16_as_ushort(lo);
}
__device__ __forceinline__ void cp16(uint32_t s, const void* g) {
    asm volatile("cp.async.cg.shared.global [%0], [%1], 16;"
                 :: "r"(s), "l"(__cvta_generic_to_global(g)) : "memory");
}
#define CP_COMMIT() asm volatile("cp.async.commit_group;" ::: "memory")
#define CP_WAIT2()  asm volatile("cp.async.wait_group 2;"  ::: "memory")

#define LDSM_X4(r0,r1,r2,r3,addr) \
    asm volatile("ldmatrix.sync.aligned.m8n8.x4.shared.b16 {%0,%1,%2,%3}, [%4];" \
                 : "=r"(r0), "=r"(r1), "=r"(r2), "=r"(r3) : "r"(addr))
#define LDSM_X4T(r0,r1,r2,r3,addr) \
    asm volatile("ldmatrix.sync.aligned.m8n8.x4.trans.shared.b16 {%0,%1,%2,%3}, [%4];" \
                 : "=r"(r0), "=r"(r1), "=r"(r2), "=r"(r3) : "r"(addr))
#define MMA_BF16(c0,c1,c2,c3,a0,a1,a2,a3,b0,b1) \
    asm volatile("mma.sync.aligned.m16n8k16.row.col.f32.bf16.bf16.f32 " \
                 "{%0,%1,%2,%3}, {%4,%5,%6,%7}, {%8,%9}, {%0,%1,%2,%3};" \
                 : "+f"(c0), "+f"(c1), "+f"(c2), "+f"(c3) \
                 : "r"(a0), "r"(a1), "r"(a2), "r"(a3), "r"(b0), "r"(b1))

// ---------------- prep kernels ----------------
__global__ void prep_M(const float* __restrict__ sup, const float* __restrict__ eps) {
    int idx = blockIdx.x * blockDim.x + threadIdx.x;
    if (idx >= 2 * (int)AS) return;
    int rest = idx & (int)(AS - 1);
    int n = rest >> 9, m = rest & 511;
    float v = sup[idx] + ((n == m) ? (1.0f + eps[0]) : 0.0f);
    bf16 h, l; split_bf16(v, h, l);
    g_Mh[idx] = h; g_Ml[idx] = l;
}

__global__ void prep_W(const float* __restrict__ w) {
    int idx = blockIdx.x * blockDim.x + threadIdx.x;   // ko*768 + d
    if (idx >= ZC * BD) return;
    int d  = idx % BD;
    int ko = idx / BD;
    int k = ko >> 6, o = ko & 63;
    int l = d >> 6, h = d & 63;
    float v = w[((size_t)l * 256 + h * 4 + k) * OUTC + o];
    bf16 hh, ll; split_bf16(v, hh, ll);
    g_Wth[idx] = hh; g_Wtl[idx] = ll;
}

__global__ void split_X(const float* __restrict__ x) {
    int idx = blockIdx.x * blockDim.x + threadIdx.x;
    if (idx >= (int)(ROWS * (size_t)BD / 4)) return;
    float4 v = ((const float4*)x)[idx];
    bf16 h0,l0,h1,l1,h2,l2,h3,l3;
    split_bf16(v.x,h0,l0); split_bf16(v.y,h1,l1);
    split_bf16(v.z,h2,l2); split_bf16(v.w,h3,l3);
    uint2 ph, pl;
    ph.x = pack2(h0,h1); ph.y = pack2(h2,h3);
    pl.x = pack2(l0,l1); pl.y = pack2(l2,l3);
    ((uint2*)g_Xh)[idx] = ph;
    ((uint2*)g_Xl)[idx] = pl;
}

// ---------------- M^2 (HMMA, split-K over 3 parts, 4-stage cp.async) -------------
// grid (NN/64, NN/128, 6); z: part = z>>1, s = z&1. CTA 128n x 64m, 16 chunks.
#define M2_APAD 40
#define M2_BPAD 72
#define M2_NCHUNK 16
#define M2_ATILE (128 * M2_APAD)
#define M2_BTILE (32 * M2_BPAD)
#define M2_SMEM ((4 * M2_ATILE + 4 * M2_BTILE) * 2)

__global__ __launch_bounds__(256, 2) void gemm_m2_mma() {
    extern __shared__ __align__(16) bf16 smm[];
    bf16* Asm = smm;
    bf16* Bsm = smm + 4 * M2_ATILE;

    const int tid = threadIdx.x;
    const int warp = tid >> 5, lane = tid & 31;
    const int wm = warp >> 1, wn = warp & 1;
    const int g = lane >> 2, q = lane & 3;
    const int part = blockIdx.z >> 1;
    const int s    = blockIdx.z & 1;
    const int n0 = blockIdx.y * 128;
    const int m0 = blockIdx.x * 64;

    const int aLdRow = tid >> 2, aLdSeg = tid & 3;
    const int bLdRow = tid >> 3, bLdSeg = tid & 7;
    const int fragRow  = lane & 15;
    const int fragCol8 = (lane >> 4) * 8;

    uint32_t aB[4], bB[4];
#pragma unroll
    for (int st = 0; st < 4; ++st) {
        aB[st] = smem_u32(Asm + st * M2_ATILE);
        bB[st] = smem_u32(Bsm + st * M2_BTILE);
    }

    const bf16* Ap = ((part == 1) ? g_Ml : g_Mh) + (size_t)s * AS;
    const bf16* Bp = ((part == 2) ? g_Ml : g_Mh) + (size_t)s * AS;

    float c[2][4][4];
#pragma unroll
    for (int i = 0; i < 2; ++i)
#pragma unroll
        for (int j = 0; j < 4; ++j)
#pragma unroll
            for (int t = 0; t < 4; ++t) c[i][j][t] = 0.f;

    auto load_stage = [&](int ch) {
        int st = ch & 3;
        int jpos = ch * 32;
        cp16(aB[st] + (uint32_t)(aLdRow * M2_APAD + aLdSeg * 8) * 2,
             Ap + (size_t)(n0 + aLdRow) * NN + jpos + aLdSeg * 8);
        cp16(aB[st] + (uint32_t)((aLdRow + 64) * M2_APAD + aLdSeg * 8) * 2,
             Ap + (size_t)(n0 + aLdRow + 64) * NN + jpos + aLdSeg * 8);
        cp16(bB[st] + (uint32_t)(bLdRow * M2_BPAD + bLdSeg * 8) * 2,
             Bp + (size_t)(jpos + bLdRow) * NN + m0 + bLdSeg * 8);
        CP_COMMIT();
    };

    load_stage(0); load_stage(1); load_stage(2);

    for (int ch = 0; ch < M2_NCHUNK; ++ch) {
        CP_WAIT2();
        __syncthreads();
        int st = ch & 3;
#pragma unroll
        for (int ks = 0; ks < 32; ks += 16) {
            uint32_t a[2][4];
#pragma unroll
            for (int i = 0; i < 2; ++i) {
                uint32_t addr = aB[st]
                    + (uint32_t)(wm * 32 + i * 16 + fragRow) * (M2_APAD * 2)
                    + (uint32_t)(ks + fragCol8) * 2;
                LDSM_X4(a[i][0], a[i][1], a[i][2], a[i][3], addr);
            }
            uint32_t b[4][2];
#pragma unroll
            for (int jj = 0; jj < 2; ++jj) {
                uint32_t addr = bB[st]
                    + (uint32_t)(ks + fragRow) * (M2_BPAD * 2)
                    + (uint32_t)(wn * 32 + jj * 16 + fragCol8) * 2;
                uint32_t r0_, r1_, r2_, r3_;
                LDSM_X4T(r0_, r1_, r2_, r3_, addr);
                b[2*jj][0] = r0_;   b[2*jj][1] = r1_;
                b[2*jj+1][0] = r2_; b[2*jj+1][1] = r3_;
            }
#pragma unroll
            for (int i = 0; i < 2; ++i)
#pragma unroll
                for (int j = 0; j < 4; ++j)
                    MMA_BF16(c[i][j][0], c[i][j][1], c[i][j][2], c[i][j][3],
                             a[i][0], a[i][1], a[i][2], a[i][3], b[j][0], b[j][1]);
        }
        if (ch + 3 < M2_NCHUNK) load_stage(ch + 3);
        else CP_COMMIT();
    }

    float* O = g_M2p + (size_t)(part * 2 + s) * AS;
#pragma unroll
    for (int i = 0; i < 2; ++i) {
        int row = n0 + wm * 32 + i * 16 + g;
#pragma unroll
        for (int j = 0; j < 4; ++j) {
            int col = m0 + wn * 32 + j * 8 + 2 * q;
            float2 v0 = { c[i][j][0], c[i][j][1] };
            float2 v1 = { c[i][j][2], c[i][j][3] };
            *(float2*)&O[(size_t)row * NN + col] = v0;
            *(float2*)&O[(size_t)(row + 8) * NN + col] = v1;
        }
    }
}

// combine 3 part-slabs (fixed order, deterministic) -> split bf16
__global__ void m2_combine() {
    int idx = blockIdx.x * blockDim.x + threadIdx.x;
    if (idx >= 2 * (int)AS) return;
    int s = idx >> 18;
    size_t rest = (size_t)(idx & (int)(AS - 1));
    float v = g_M2p[(size_t)(0 + s) * AS + rest]
            + g_M2p[(size_t)(2 + s) * AS + rest]
            + g_M2p[(size_t)(4 + s) * AS + rest];
    bf16 h, l; split_bf16(v, h, l);
    g_M2h[idx] = h; g_M2l[idx] = l;
}

// ---------------- stage1 (HMMA, 4-stage cp.async, occ 2): Z = XhWh+XlWh+XhWl -----
#define S1_PAD 40
#define S1_NCHUNK 72          // 3 parts * 768/32
#define S1_TILE (128 * S1_PAD)
#define S1_SMEM (8 * S1_TILE * 2)   // 4 A stages + 4 B stages, bytes

__global__ __launch_bounds__(256, 2) void stage1_mma() {
    extern __shared__ __align__(16) bf16 sm1[];
    bf16* Asm = sm1;                  // [4][S1_TILE]
    bf16* Bsm = sm1 + 4 * S1_TILE;    // [4][S1_TILE]

    const int tid = threadIdx.x;
    const int warp = tid >> 5, lane = tid & 31;
    const int wm = warp >> 1, wn = warp & 1;
    const int g = lane >> 2, q = lane & 3;
    const int r0 = blockIdx.y * 128;
    const int c0 = blockIdx.x * 128;

    const int ldrow = tid >> 2;
    const int ldseg = tid & 3;

    // round-5 validated lane-invariant ldmatrix offsets
    const int aRowOff = ((lane >> 3) & 1) * 8 + (lane & 7);
    const int aKOff   = (lane >> 4) * 8;
    const int bRowOff = (lane >> 4) * 8 + (lane & 7);
    const int bKOff   = ((lane >> 3) & 1) * 8;

    uint32_t aB[4], bB[4];
#pragma unroll
    for (int st = 0; st < 4; ++st) {
        aB[st] = smem_u32(Asm + st * S1_TILE);
        bB[st] = smem_u32(Bsm + st * S1_TILE);
    }

    float c[2][8][4];
#pragma unroll
    for (int i = 0; i < 2; ++i)
#pragma unroll
        for (int j = 0; j < 8; ++j)
#pragma unroll
            for (int t = 0; t < 4; ++t) c[i][j][t] = 0.f;

    auto load_stage = [&](int ch) {
        int st = ch & 3;
        int part = ch / 24;
        int kpos = (ch % 24) * 32;
        const bf16* Ap = (part == 1) ? g_Xl : g_Xh;
        const bf16* Bp = (part == 2) ? g_Wtl : g_Wth;
#pragma unroll
        for (int t = 0; t < 2; ++t) {
            int row = ldrow + t * 64;
            uint32_t so = (uint32_t)(row * S1_PAD + ldseg * 8) * 2;
            cp16(aB[st] + so, Ap + (size_t)(r0 + row) * BD + kpos + ldseg * 8);
            cp16(bB[st] + so, Bp + (size_t)(c0 + row) * BD + kpos + ldseg * 8);
        }
        CP_COMMIT();
    };

    load_stage(0); load_stage(1); load_stage(2);

    for (int ch = 0; ch < S1_NCHUNK; ++ch) {
        CP_WAIT2();
        __syncthreads();
        int st = ch & 3;
#pragma unroll
        for (int ks = 0; ks < 32; ks += 16) {
            uint32_t a[2][4];
#pragma unroll
            for (int i = 0; i < 2; ++i) {
                uint32_t addr = aB[st]
                    + (uint32_t)(wm * 32 + i * 16 + aRowOff) * (S1_PAD * 2)
                    + (uint32_t)(ks + aKOff) * 2;
                LDSM_X4(a[i][0], a[i][1], a[i][2], a[i][3], addr);
            }
            uint32_t b[8][2];
#pragma unroll
            for (int j2 = 0; j2 < 4; ++j2) {
                uint32_t addr = bB[st]
                    + (uint32_t)(wn * 64 + j2 * 16 + bRowOff) * (S1_PAD * 2)
                    + (uint32_t)(ks + bKOff) * 2;
                uint32_t r0_, r1_, r2_, r3_;
                LDSM_X4(r0_, r1_, r2_, r3_, addr);
                b[2*j2][0]   = r0_; b[2*j2][1]   = r1_;
                b[2*j2+1][0] = r2_; b[2*j2+1][1] = r3_;
            }
#pragma unroll
            for (int i = 0; i < 2; ++i)
#pragma unroll
                for (int j = 0; j < 8; ++j)
                    MMA_BF16(c[i][j][0], c[i][j][1], c[i][j][2], c[i][j][3],
                             a[i][0], a[i][1], a[i][2], a[i][3], b[j][0], b[j][1]);
        }
        if (ch + 3 < S1_NCHUNK) load_stage(ch + 3);
        else CP_COMMIT();   // empty group keeps wait(2) arithmetic exact at tail
    }

    // epilogue: split fp32 -> Zh/Zl bf16
#pragma unroll
    for (int i = 0; i < 2; ++i) {
        int row = r0 + wm * 32 + i * 16 + g;
#pragma unroll
        for (int j = 0; j < 8; ++j) {
            int col = c0 + wn * 64 + j * 8 + 2 * q;
#pragma unroll
            for (int hrow = 0; hrow < 2; ++hrow) {
                float v0 = c[i][j][hrow * 2], v1 = c[i][j][hrow * 2 + 1];
                bf16 h0, l0, h1, l1;
                split_bf16(v0, h0, l0); split_bf16(v1, h1, l1);
                size_t off = (size_t)(row + hrow * 8) * ZC + col;
                *(uint32_t*)&g_Zh[off] = pack2(h0, h1);
                *(uint32_t*)&g_Zl[off] = pack2(l0, l1);
            }
        }
    }
}

// ---------------- stage2 (HMMA, 4-stage cp.async, split-K x2) --------------------
// grid (NN/128, BB, 2); z half processes 96 of 192 chunks into fp32 slab z.
#define S2_APAD 40
#define S2_BPAD 72
#define S2_HCHUNK 96
#define S2_ATILE (128 * S2_APAD)
#define S2_BTILE (32 * S2_BPAD)
#define S2_SMEM ((4 * S2_ATILE + 4 * S2_BTILE) * 2)

__global__ __launch_bounds__(256, 2) void stage2_mma() {
    extern __shared__ __align__(16) bf16 sm2[];
    bf16* Asm = sm2;
    bf16* Bsm = sm2 + 4 * S2_ATILE;

    const int tid = threadIdx.x;
    const int warp = tid >> 5, lane = tid & 31;
    const int wm = warp >> 1, wn = warp & 1;
    const int g = lane >> 2, q = lane & 3;
    const int n0 = blockIdx.x * 128;
    const int b  = blockIdx.y;
    const int ch0 = blockIdx.z * S2_HCHUNK;

    const int aLdRow = tid >> 2, aLdSeg = tid & 3;
    const int bLdRow = tid >> 3, bLdSeg = tid & 7;
    const int fragRow  = lane & 15;
    const int fragCol8 = (lane >> 4) * 8;

    uint32_t aB[4], bB[4];
#pragma unroll
    for (int st = 0; st < 4; ++st) {
        aB[st] = smem_u32(Asm + st * S2_ATILE);
        bB[st] = smem_u32(Bsm + st * S2_BTILE);
    }

    float c[2][4][4];
#pragma unroll
    for (int i = 0; i < 2; ++i)
#pragma unroll
        for (int j = 0; j < 4; ++j)
#pragma unroll
            for (int t = 0; t < 4; ++t) c[i][j][t] = 0.f;

    auto load_stage = [&](int ch) {
        int st = ch & 3;
        int part = ch >> 6;          // 0,1,2
        int rem = ch & 63;
        int k = rem >> 4;            // 0..3
        int mpos = (rem & 15) * 32;
        const bf16* Am;
        if (part == 1) Am = (k & 1) ? g_M2l : g_Ml;
        else           Am = (k & 1) ? g_M2h : g_Mh;
        Am += (size_t)(k >> 1) * AS;
        cp16(aB[st] + (uint32_t)(aLdRow * S2_APAD + aLdSeg * 8) * 2,
             Am + (size_t)(n0 + aLdRow) * NN + mpos + aLdSeg * 8);
        cp16(aB[st] + (uint32_t)((aLdRow + 64) * S2_APAD + aLdSeg * 8) * 2,
             Am + (size_t)(n0 + aLdRow + 64) * NN + mpos + aLdSeg * 8);
        const bf16* Zp = (part == 2) ? g_Zl : g_Zh;
        cp16(bB[st] + (uint32_t)(bLdRow * S2_BPAD + bLdSeg * 8) * 2,
             Zp + (size_t)(b * NN + mpos + bLdRow) * ZC + k * 64 + bLdSeg * 8);
        CP_COMMIT();
    };

    load_stage(ch0); load_stage(ch0 + 1); load_stage(ch0 + 2);

    for (int i2 = 0; i2 < S2_HCHUNK; ++i2) {
        int ch = ch0 + i2;
        CP_WAIT2();
        __syncthreads();
        int st = ch & 3;
#pragma unroll
        for (int ks = 0; ks < 32; ks += 16) {
            uint32_t a[2][4];
#pragma unroll
            for (int i = 0; i < 2; ++i) {
                uint32_t addr = aB[st]
                    + (uint32_t)(wm * 32 + i * 16 + fragRow) * (S2_APAD * 2)
                    + (uint32_t)(ks + fragCol8) * 2;
                LDSM_X4(a[i][0], a[i][1], a[i][2], a[i][3], addr);
            }
            uint32_t b_[4][2];
#pragma unroll
            for (int jj = 0; jj < 2; ++jj) {
                uint32_t addr = bB[st]
                    + (uint32_t)(ks + fragRow) * (S2_BPAD * 2)
                    + (uint32_t)(wn * 32 + jj * 16 + fragCol8) * 2;
                uint32_t r0_, r1_, r2_, r3_;
                LDSM_X4T(r0_, r1_, r2_, r3_, addr);
                b_[2*jj][0] = r0_;   b_[2*jj][1] = r1_;
                b_[2*jj+1][0] = r2_; b_[2*jj+1][1] = r3_;
            }
#pragma unroll
            for (int i = 0; i < 2; ++i)
#pragma unroll
                for (int j = 0; j < 4; ++j)
                    MMA_BF16(c[i][j][0], c[i][j][1], c[i][j][2], c[i][j][3],
                             a[i][0], a[i][1], a[i][2], a[i][3], b_[j][0], b_[j][1]);
        }
        if (i2 + 3 < S2_HCHUNK) load_stage(ch + 3);
        else CP_COMMIT();
    }

    // epilogue: fp32 -> slab z
    float* O = g_midp[blockIdx.z];
#pragma unroll
    for (int i = 0; i < 2; ++i) {
        int row = n0 + wm * 32 + i * 16 + g;
#pragma unroll
        for (int j = 0; j < 4; ++j) {
            int col = wn * 32 + j * 8 + 2 * q;
            float2 v0 = { c[i][j][0], c[i][j][1] };
            float2 v1 = { c[i][j][2], c[i][j][3] };
            *(float2*)&O[(size_t)(b * NN + row) * OUTC + col] = v0;
            *(float2*)&O[(size_t)(b * NN + row + 8) * OUTC + col] = v1;
        }
    }
}

// combine stage2 slabs -> g_mid (deterministic order)
__global__ void mid_combine() {
    int idx = blockIdx.x * blockDim.x + threadIdx.x;
    if (idx >= (int)(ROWS * (size_t)OUTC / 4)) return;
    float4 a = ((const float4*)g_midp[0])[idx];
    float4 b = ((const float4*)g_midp[1])[idx];
    float4 v = { a.x + b.x, a.y + b.y, a.z + b.z, a.w + b.w };
    ((float4*)g_mid)[idx] = v;
}

// ---------------- BN tail ----------------
__global__ void zero_stats() {
    if (threadIdx.x < OUTC) { g_sum[threadIdx.x] = 0.f; g_sumsq[threadIdx.x] = 0.f; }
}
__global__ __launch_bounds__(256) void bn_stats() {
    const int c = threadIdx.x & 63;
    const int rl = threadIdx.x >> 6;
    float s = 0.f, s2 = 0.f;
    for (int r = blockIdx.x * 4 + rl; r < ROWS; r += gridDim.x * 4) {
        float v = g_mid[(size_t)r * OUTC + c];
        s += v; s2 += v * v;
    }
    __shared__ float sh[256], sh2[256];
    sh[threadIdx.x] = s; sh2[threadIdx.x] = s2;
    __syncthreads();
    if (rl == 0) {
        s  = sh[c] + sh[c + 64] + sh[c + 128] + sh[c + 192];
        s2 = sh2[c] + sh2[c + 64] + sh2[c + 128] + sh2[c + 192];
        atomicAdd(&g_sum[c], s); atomicAdd(&g_sumsq[c], s2);
    }
}
__global__ __launch_bounds__(256) void bn_relu_fc2(
    const float* __restrict__ gamma, const float* __restrict__ beta,
    const float* __restrict__ w2,    const float* __restrict__ b2,
    float* __restrict__ out)
{
    __shared__ float w2t[64][65];
    __shared__ float ysm[64][65];
    __shared__ float scale_s[64], shift_s[64];
    const int tid = threadIdx.x;
    const int r0 = blockIdx.x * 64;

#pragma unroll
    for (int t = 0; t < 16; ++t) {
        int idx = tid + t * 256;
        int o = idx >> 6, cc = idx & 63;
        w2t[cc][o] = w2[idx];
    }
    if (tid < OUTC) {
        const float invN = 1.0f / (float)ROWS;
        float mean = g_sum[tid] * invN;
        float var  = g_sumsq[tid] * invN - mean * mean;
        float sc   = gamma[tid] * rsqrtf(var + 1e-5f);
        scale_s[tid] = sc;
        shift_s[tid] = beta[tid] - mean * sc;
    }
    __syncthreads();

#pragma unroll
    for (int t = 0; t < 16; ++t) {
        int idx = tid + t * 256;
        int r = idx >> 6, cc = idx & 63;
        float v = g_mid[(size_t)(r0 + r) * OUTC + cc];
        ysm[r][cc] = fmaxf(fmaf(v, scale_s[cc], shift_s[cc]), 0.f);
    }
    __syncthreads();

    const int tr = tid >> 4, tc = tid & 15;
    float acc[4][4];
#pragma unroll
    for (int i = 0; i < 4; ++i)
#pragma unroll
        for (int j = 0; j < 4; ++j) acc[i][j] = b2[tc * 4 + j];
    for (int k = 0; k < 64; ++k) {
        float w0 = w2t[k][tc * 4 + 0], w1 = w2t[k][tc * 4 + 1];
        float w2v = w2t[k][tc * 4 + 2], w3 = w2t[k][tc * 4 + 3];
#pragma unroll
        for (int i = 0; i < 4; ++i) {
            float y = ysm[tr * 4 + i][k];
            acc[i][0] = fmaf(y, w0, acc[i][0]);
            acc[i][1] = fmaf(y, w1, acc[i][1]);
            acc[i][2] = fmaf(y, w2v, acc[i][2]);
            acc[i][3] = fmaf(y, w3, acc[i][3]);
        }
    }
#pragma unroll
    for (int i = 0; i < 4; ++i)
        *(float4*)&out[(size_t)(r0 + tr * 4 + i) * OUTC + tc * 4] = *(float4*)&acc[i][0];
}

// ---------------- launch ----------------
extern "C" void kernel_launch(void* const* d_in, const int* in_sizes, int n_in,
                              void* d_out, int out_size) {
    const float* x       = (const float*)d_in[0];
    const float* support = (const float*)d_in[1];
    const float* weight  = (const float*)d_in[2];
    const float* eps     = (const float*)d_in[3];
    const float* gamma   = (const float*)d_in[4];
    const float* beta    = (const float*)d_in[5];
    const float* w2      = (const float*)d_in[6];
    const float* b2      = (const float*)d_in[7];
    float* out           = (float*)d_out;

    cudaFuncSetAttribute(gemm_m2_mma, cudaFuncAttributeMaxDynamicSharedMemorySize, M2_SMEM);
    cudaFuncSetAttribute(stage1_mma, cudaFuncAttributeMaxDynamicSharedMemorySize, S1_SMEM);
    cudaFuncSetAttribute(stage2_mma, cudaFuncAttributeMaxDynamicSharedMemorySize, S2_SMEM);

    prep_M<<<(2 * (int)AS + 255) / 256, 256>>>(support, eps);
    prep_W<<<(ZC * BD + 255) / 256, 256>>>(weight);
    split_X<<<(int)(ROWS * (size_t)BD / 4 + 255) / 256, 256>>>(x);

    gemm_m2_mma<<<dim3(NN / 64, NN / 128, 6), 256, M2_SMEM>>>();
    m2_combine<<<(2 * (int)AS + 255) / 256, 256>>>();

    stage1_mma<<<dim3(ZC / 128, ROWS / 128), 256, S1_SMEM>>>();

    stage2_mma<<<dim3(NN / 128, BB, 2), 256, S2_SMEM>>>();
    mid_combine<<<(int)(ROWS * (size_t)OUTC / 4 + 255) / 256, 256>>>();

    zero_stats<<<1, 64>>>();
    bn_stats<<<128, 256>>>();
    bn_relu_fc2<<<ROWS / 64, 256>>>(gamma, beta, w2, b2, out);
}

// round 10
// speedup vs baseline: 13.8096x; 1.0437x over previous
#include <cuda_runtime.h>
#include <cuda_bf16.h>
#include <math.h>
#include <stdint.h>

typedef __nv_bfloat16 bf16;

// ---------------- problem dims ----------------
#define BB    32
#define NN    512
#define BD    768            // L*H
#define ROWS  (BB*NN)        // 16384
#define OUTC  64
#define KSUP  4
#define ZC    256            // KSUP*OUTC
#define AS    ((size_t)NN*NN)

// ---------------- device scratch (no allocation) ----------------
__device__ __align__(256) bf16  g_Mh [2*AS], g_Ml [2*AS];    // M = A+(1+eps)I, split
__device__ __align__(256) bf16  g_Xh[(size_t)ROWS*BD], g_Xl[(size_t)ROWS*BD];
__device__ __align__(256) bf16  g_Wth[ZC*BD], g_Wtl[ZC*BD];  // W^T repack [ko][d]
__device__ __align__(256) bf16  g_Zh[(size_t)ROWS*ZC], g_Zl[(size_t)ROWS*ZC];
__device__ __align__(256) float g_U [(size_t)2*ROWS*OUTC];   // U_s = M_s Z_odd
__device__ __align__(256) bf16  g_Vh[(size_t)2*ROWS*OUTC], g_Vl[(size_t)2*ROWS*OUTC];
__device__ __align__(256) float g_midp[2][(size_t)ROWS*OUTC]; // stage2b slabs (per s)
__device__ float g_sum[OUTC], g_sumsq[OUTC];

__device__ __forceinline__ uint32_t smem_u32(const void* p) {
    uint32_t a;
    asm("{ .reg .u64 t; cvta.to.shared.u64 t, %1; cvt.u32.u64 %0, t; }" : "=r"(a) : "l"(p));
    return a;
}
__device__ __forceinline__ void split_bf16(float v, bf16& h, bf16& l) {
    h = __float2bfloat16(v);
    l = __float2bfloat16(v - __bfloat162float(h));
}
__device__ __forceinline__ uint32_t pack2(bf16 lo, bf16 hi) {
    return ((uint32_t)__bfloat16_as_ushort(hi) << 16) | __bfloat16_as_ushort(lo);
}
__device__ __forceinline__ void cp16(uint32_t s, const void* g) {
    asm volatile("cp.async.cg.shared.global [%0], [%1], 16;"
                 :: "r"(s), "l"(__cvta_generic_to_global(g)) : "memory");
}
#define CP_COMMIT() asm volatile("cp.async.commit_group;" ::: "memory")
#define CP_WAIT1()  asm volatile("cp.async.wait_group 1;"  ::: "memory")
#define CP_WAIT2()  asm volatile("cp.async.wait_group 2;"  ::: "memory")

#define LDSM_X4(r0,r1,r2,r3,addr) \
    asm volatile("ldmatrix.sync.aligned.m8n8.x4.shared.b16 {%0,%1,%2,%3}, [%4];" \
                 : "=r"(r0), "=r"(r1), "=r"(r2), "=r"(r3) : "r"(addr))
#define LDSM_X4T(r0,r1,r2,r3,addr) \
    asm volatile("ldmatrix.sync.aligned.m8n8.x4.trans.shared.b16 {%0,%1,%2,%3}, [%4];" \
                 : "=r"(r0), "=r"(r1), "=r"(r2), "=r"(r3) : "r"(addr))
#define MMA_BF16(c0,c1,c2,c3,a0,a1,a2,a3,b0,b1) \
    asm volatile("mma.sync.aligned.m16n8k16.row.col.f32.bf16.bf16.f32 " \
                 "{%0,%1,%2,%3}, {%4,%5,%6,%7}, {%8,%9}, {%0,%1,%2,%3};" \
                 : "+f"(c0), "+f"(c1), "+f"(c2), "+f"(c3) \
                 : "r"(a0), "r"(a1), "r"(a2), "r"(a3), "r"(b0), "r"(b1))

// ---------------- prep kernels ----------------
__global__ void prep_M(const float* __restrict__ sup, const float* __restrict__ eps) {
    int idx = blockIdx.x * blockDim.x + threadIdx.x;
    if (idx >= 2 * (int)AS) return;
    int rest = idx & (int)(AS - 1);
    int n = rest >> 9, m = rest & 511;
    float v = sup[idx] + ((n == m) ? (1.0f + eps[0]) : 0.0f);
    bf16 h, l; split_bf16(v, h, l);
    g_Mh[idx] = h; g_Ml[idx] = l;
}

__global__ void prep_W(const float* __restrict__ w) {
    int idx = blockIdx.x * blockDim.x + threadIdx.x;   // ko*768 + d
    if (idx >= ZC * BD) return;
    int d  = idx % BD;
    int ko = idx / BD;
    int k = ko >> 6, o = ko & 63;
    int l = d >> 6, h = d & 63;
    float v = w[((size_t)l * 256 + h * 4 + k) * OUTC + o];
    bf16 hh, ll; split_bf16(v, hh, ll);
    g_Wth[idx] = hh; g_Wtl[idx] = ll;
}

__global__ void split_X(const float* __restrict__ x) {
    int idx = blockIdx.x * blockDim.x + threadIdx.x;
    if (idx >= (int)(ROWS * (size_t)BD / 4)) return;
    float4 v = ((const float4*)x)[idx];
    bf16 h0,l0,h1,l1,h2,l2,h3,l3;
    split_bf16(v.x,h0,l0); split_bf16(v.y,h1,l1);
    split_bf16(v.z,h2,l2); split_bf16(v.w,h3,l3);
    uint2 ph, pl;
    ph.x = pack2(h0,h1); ph.y = pack2(h2,h3);
    pl.x = pack2(l0,l1); pl.y = pack2(l2,l3);
    ((uint2*)g_Xh)[idx] = ph;
    ((uint2*)g_Xl)[idx] = pl;
}

// ---------------- stage1 (HMMA, BK=64, 3-stage cp.async, occ 2) ------------------
#define S1_PAD 72
#define S1_NCHUNK 36          // 3 parts * 768/64
#define S1_TILE (128 * S1_PAD)
#define S1_SMEM (6 * S1_TILE * 2)   // 3 A + 3 B stages

__global__ __launch_bounds__(256, 2) void stage1_mma() {
    extern __shared__ __align__(16) bf16 sm1[];
    bf16* Asm = sm1;
    bf16* Bsm = sm1 + 3 * S1_TILE;

    const int tid = threadIdx.x;
    const int warp = tid >> 5, lane = tid & 31;
    const int wm = warp >> 1, wn = warp & 1;
    const int g = lane >> 2, q = lane & 3;
    const int r0 = blockIdx.y * 128;
    const int c0 = blockIdx.x * 128;

    // round-5 validated lane-invariant ldmatrix offsets
    const int aRowOff = ((lane >> 3) & 1) * 8 + (lane & 7);
    const int aKOff   = (lane >> 4) * 8;
    const int bRowOff = (lane >> 4) * 8 + (lane & 7);
    const int bKOff   = ((lane >> 3) & 1) * 8;

    uint32_t aB[3], bB[3];
#pragma unroll
    for (int st = 0; st < 3; ++st) {
        aB[st] = smem_u32(Asm + st * S1_TILE);
        bB[st] = smem_u32(Bsm + st * S1_TILE);
    }

    float c[2][8][4];
#pragma unroll
    for (int i = 0; i < 2; ++i)
#pragma unroll
        for (int j = 0; j < 8; ++j)
#pragma unroll
            for (int t = 0; t < 4; ++t) c[i][j][t] = 0.f;

    auto load_stage = [&](int ch) {
        int st = ch % 3;
        int part = ch / 12;
        int kpos = (ch % 12) * 64;
        const bf16* Ap = (part == 1) ? g_Xl : g_Xh;
        const bf16* Bp = (part == 2) ? g_Wtl : g_Wth;
#pragma unroll
        for (int t = 0; t < 4; ++t) {
            int u = tid + t * 256;
            int row = u >> 3, seg = u & 7;
            uint32_t so = (uint32_t)(row * S1_PAD + seg * 8) * 2;
            cp16(aB[st] + so, Ap + (size_t)(r0 + row) * BD + kpos + seg * 8);
            cp16(bB[st] + so, Bp + (size_t)(c0 + row) * BD + kpos + seg * 8);
        }
        CP_COMMIT();
    };

    load_stage(0); load_stage(1);

#pragma unroll 3
    for (int ch = 0; ch < S1_NCHUNK; ++ch) {
        CP_WAIT1();
        __syncthreads();
        int st = ch % 3;
#pragma unroll
        for (int ks = 0; ks < 64; ks += 16) {
            uint32_t a[2][4];
#pragma unroll
            for (int i = 0; i < 2; ++i) {
                uint32_t addr = aB[st]
                    + (uint32_t)(wm * 32 + i * 16 + aRowOff) * (S1_PAD * 2)
                    + (uint32_t)(ks + aKOff) * 2;
                LDSM_X4(a[i][0], a[i][1], a[i][2], a[i][3], addr);
            }
            uint32_t b[8][2];
#pragma unroll
            for (int j2 = 0; j2 < 4; ++j2) {
                uint32_t addr = bB[st]
                    + (uint32_t)(wn * 64 + j2 * 16 + bRowOff) * (S1_PAD * 2)
                    + (uint32_t)(ks + bKOff) * 2;
                uint32_t r0_, r1_, r2_, r3_;
                LDSM_X4(r0_, r1_, r2_, r3_, addr);
                b[2*j2][0]   = r0_; b[2*j2][1]   = r1_;
                b[2*j2+1][0] = r2_; b[2*j2+1][1] = r3_;
            }
#pragma unroll
            for (int i = 0; i < 2; ++i)
#pragma unroll
                for (int j = 0; j < 8; ++j)
                    MMA_BF16(c[i][j][0], c[i][j][1], c[i][j][2], c[i][j][3],
                             a[i][0], a[i][1], a[i][2], a[i][3], b[j][0], b[j][1]);
        }
        if (ch + 2 < S1_NCHUNK) load_stage(ch + 2);
        else CP_COMMIT();   // empty group keeps wait(1) arithmetic exact at tail
    }

    // epilogue: split fp32 -> Zh/Zl bf16
#pragma unroll
    for (int i = 0; i < 2; ++i) {
        int row = r0 + wm * 32 + i * 16 + g;
#pragma unroll
        for (int j = 0; j < 8; ++j) {
            int col = c0 + wn * 64 + j * 8 + 2 * q;
#pragma unroll
            for (int hrow = 0; hrow < 2; ++hrow) {
                float v0 = c[i][j][hrow * 2], v1 = c[i][j][hrow * 2 + 1];
                bf16 h0, l0, h1, l1;
                split_bf16(v0, h0, l0); split_bf16(v1, h1, l1);
                size_t off = (size_t)(row + hrow * 8) * ZC + col;
                *(uint32_t*)&g_Zh[off] = pack2(h0, h1);
                *(uint32_t*)&g_Zl[off] = pack2(l0, l1);
            }
        }
    }
}

// ---------------- stage2a (HMMA): U_s = M_s * Z[:,64(2s+1):...] ------------------
// grid (4, BB, 2); z = s. 48 chunks of BK=32 (3 parts * 512/32).
#define S2_APAD 40
#define S2_BPAD 72
#define S2_NCH 48
#define S2_ATILE (128 * S2_APAD)
#define S2_BTILE (32 * S2_BPAD)
#define S2_SMEM ((4 * S2_ATILE + 4 * S2_BTILE) * 2)

__global__ __launch_bounds__(256, 2) void stage2a_mma() {
    extern __shared__ __align__(16) bf16 sm2[];
    bf16* Asm = sm2;
    bf16* Bsm = sm2 + 4 * S2_ATILE;

    const int tid = threadIdx.x;
    const int warp = tid >> 5, lane = tid & 31;
    const int wm = warp >> 1, wn = warp & 1;
    const int g = lane >> 2, q = lane & 3;
    const int n0 = blockIdx.x * 128;
    const int b  = blockIdx.y;
    const int s  = blockIdx.z;

    const int aLdRow = tid >> 2, aLdSeg = tid & 3;
    const int bLdRow = tid >> 3, bLdSeg = tid & 7;
    const int fragRow  = lane & 15;
    const int fragCol8 = (lane >> 4) * 8;

    uint32_t aB[4], bB[4];
#pragma unroll
    for (int st = 0; st < 4; ++st) {
        aB[st] = smem_u32(Asm + st * S2_ATILE);
        bB[st] = smem_u32(Bsm + st * S2_BTILE);
    }

    float c[2][4][4];
#pragma unroll
    for (int i = 0; i < 2; ++i)
#pragma unroll
        for (int j = 0; j < 4; ++j)
#pragma unroll
            for (int t = 0; t < 4; ++t) c[i][j][t] = 0.f;

    const int zcol = (2 * s + 1) * 64;

    auto load_stage = [&](int ch) {
        int st = ch & 3;
        int part = ch >> 4;          // 0,1,2
        int mpos = (ch & 15) * 32;
        const bf16* Am = ((part == 1) ? g_Ml : g_Mh) + (size_t)s * AS;
        cp16(aB[st] + (uint32_t)(aLdRow * S2_APAD + aLdSeg * 8) * 2,
             Am + (size_t)(n0 + aLdRow) * NN + mpos + aLdSeg * 8);
        cp16(aB[st] + (uint32_t)((aLdRow + 64) * S2_APAD + aLdSeg * 8) * 2,
             Am + (size_t)(n0 + aLdRow + 64) * NN + mpos + aLdSeg * 8);
        const bf16* Zp = (part == 2) ? g_Zl : g_Zh;
        cp16(bB[st] + (uint32_t)(bLdRow * S2_BPAD + bLdSeg * 8) * 2,
             Zp + (size_t)(b * NN + mpos + bLdRow) * ZC + zcol + bLdSeg * 8);
        CP_COMMIT();
    };

    load_stage(0); load_stage(1); load_stage(2);

    for (int ch = 0; ch < S2_NCH; ++ch) {
        CP_WAIT2();
        __syncthreads();
        int st = ch & 3;
#pragma unroll
        for (int ks = 0; ks < 32; ks += 16) {
            uint32_t a[2][4];
#pragma unroll
            for (int i = 0; i < 2; ++i) {
                uint32_t addr = aB[st]
                    + (uint32_t)(wm * 32 + i * 16 + fragRow) * (S2_APAD * 2)
                    + (uint32_t)(ks + fragCol8) * 2;
                LDSM_X4(a[i][0], a[i][1], a[i][2], a[i][3], addr);
            }
            uint32_t b_[4][2];
#pragma unroll
            for (int jj = 0; jj < 2; ++jj) {
                uint32_t addr = bB[st]
                    + (uint32_t)(ks + fragRow) * (S2_BPAD * 2)
                    + (uint32_t)(wn * 32 + jj * 16 + fragCol8) * 2;
                uint32_t r0_, r1_, r2_, r3_;
                LDSM_X4T(r0_, r1_, r2_, r3_, addr);
                b_[2*jj][0] = r0_;   b_[2*jj][1] = r1_;
                b_[2*jj+1][0] = r2_; b_[2*jj+1][1] = r3_;
            }
#pragma unroll
            for (int i = 0; i < 2; ++i)
#pragma unroll
                for (int j = 0; j < 4; ++j)
                    MMA_BF16(c[i][j][0], c[i][j][1], c[i][j][2], c[i][j][3],
                             a[i][0], a[i][1], a[i][2], a[i][3], b_[j][0], b_[j][1]);
        }
        if (ch + 3 < S2_NCH) load_stage(ch + 3);
        else CP_COMMIT();
    }

    // epilogue: U fp32, layout ((s*BB+b)*NN + row)*64 + col
    float* O = g_U + ((size_t)(s * BB + b) * NN) * OUTC;
#pragma unroll
    for (int i = 0; i < 2; ++i) {
        int row = n0 + wm * 32 + i * 16 + g;
#pragma unroll
        for (int j = 0; j < 4; ++j) {
            int col = wn * 32 + j * 8 + 2 * q;
            float2 v0 = { c[i][j][0], c[i][j][1] };
            float2 v1 = { c[i][j][2], c[i][j][3] };
            *(float2*)&O[(size_t)row * OUTC + col] = v0;
            *(float2*)&O[(size_t)(row + 8) * OUTC + col] = v1;
        }
    }
}

// ---------------- vadd_split: V_s = Z_{2s} + U_s, split to bf16 ------------------
__global__ void vadd_split() {
    int p = blockIdx.x * blockDim.x + threadIdx.x;       // pair index
    const int NP = 2 * ROWS * 32;                        // 1,048,576
    if (p >= NP) return;
    int o2 = p & 31;
    int rest = p >> 5;
    int n = rest & 511;
    int sb = rest >> 9;
    int b = sb & 31, s = sb >> 5;
    size_t zoff = ((size_t)(b * NN + n)) * ZC + s * 128 + o2 * 2;
    uint32_t zh = *(const uint32_t*)&g_Zh[zoff];
    uint32_t zl = *(const uint32_t*)&g_Zl[zoff];
    float u0 = g_U[(size_t)p * 2], u1 = g_U[(size_t)p * 2 + 1];
    float v0 = __bfloat162float(__ushort_as_bfloat16((unsigned short)(zh & 0xFFFF)))
             + __bfloat162float(__ushort_as_bfloat16((unsigned short)(zl & 0xFFFF))) + u0;
    float v1 = __bfloat162float(__ushort_as_bfloat16((unsigned short)(zh >> 16)))
             + __bfloat162float(__ushort_as_bfloat16((unsigned short)(zl >> 16))) + u1;
    bf16 h0, l0, h1, l1;
    split_bf16(v0, h0, l0); split_bf16(v1, h1, l1);
    ((uint32_t*)g_Vh)[p] = pack2(h0, h1);
    ((uint32_t*)g_Vl)[p] = pack2(l0, l1);
}

// ---------------- stage2b (HMMA): midp[s] = M_s * V_s ----------------------------
// grid (4, BB, 2); z = s (also output slab). 48 chunks BK=32.
__global__ __launch_bounds__(256, 2) void stage2b_mma() {
    extern __shared__ __align__(16) bf16 sm3[];
    bf16* Asm = sm3;
    bf16* Bsm = sm3 + 4 * S2_ATILE;

    const int tid = threadIdx.x;
    const int warp = tid >> 5, lane = tid & 31;
    const int wm = warp >> 1, wn = warp & 1;
    const int g = lane >> 2, q = lane & 3;
    const int n0 = blockIdx.x * 128;
    const int b  = blockIdx.y;
    const int s  = blockIdx.z;

    const int aLdRow = tid >> 2, aLdSeg = tid & 3;
    const int bLdRow = tid >> 3, bLdSeg = tid & 7;
    const int fragRow  = lane & 15;
    const int fragCol8 = (lane >> 4) * 8;

    uint32_t aB[4], bB[4];
#pragma unroll
    for (int st = 0; st < 4; ++st) {
        aB[st] = smem_u32(Asm + st * S2_ATILE);
        bB[st] = smem_u32(Bsm + st * S2_BTILE);
    }

    float c[2][4][4];
#pragma unroll
    for (int i = 0; i < 2; ++i)
#pragma unroll
        for (int j = 0; j < 4; ++j)
#pragma unroll
            for (int t = 0; t < 4; ++t) c[i][j][t] = 0.f;

    const size_t vbase = ((size_t)(s * BB + b) * NN) * OUTC;

    auto load_stage = [&](int ch) {
        int st = ch & 3;
        int part = ch >> 4;          // 0,1,2
        int mpos = (ch & 15) * 32;
        const bf16* Am = ((part == 1) ? g_Ml : g_Mh) + (size_t)s * AS;
        cp16(aB[st] + (uint32_t)(aLdRow * S2_APAD + aLdSeg * 8) * 2,
             Am + (size_t)(n0 + aLdRow) * NN + mpos + aLdSeg * 8);
        cp16(aB[st] + (uint32_t)((aLdRow + 64) * S2_APAD + aLdSeg * 8) * 2,
             Am + (size_t)(n0 + aLdRow + 64) * NN + mpos + aLdSeg * 8);
        const bf16* Vp = (part == 2) ? g_Vl : g_Vh;
        cp16(bB[st] + (uint32_t)(bLdRow * S2_BPAD + bLdSeg * 8) * 2,
             Vp + vbase + (size_t)(mpos + bLdRow) * OUTC + bLdSeg * 8);
        CP_COMMIT();
    };

    load_stage(0); load_stage(1); load_stage(2);

    for (int ch = 0; ch < S2_NCH; ++ch) {
        CP_WAIT2();
        __syncthreads();
        int st = ch & 3;
#pragma unroll
        for (int ks = 0; ks < 32; ks += 16) {
            uint32_t a[2][4];
#pragma unroll
            for (int i = 0; i < 2; ++i) {
                uint32_t addr = aB[st]
                    + (uint32_t)(wm * 32 + i * 16 + fragRow) * (S2_APAD * 2)
                    + (uint32_t)(ks + fragCol8) * 2;
                LDSM_X4(a[i][0], a[i][1], a[i][2], a[i][3], addr);
            }
            uint32_t b_[4][2];
#pragma unroll
            for (int jj = 0; jj < 2; ++jj) {
                uint32_t addr = bB[st]
                    + (uint32_t)(ks + fragRow) * (S2_BPAD * 2)
                    + (uint32_t)(wn * 32 + jj * 16 + fragCol8) * 2;
                uint32_t r0_, r1_, r2_, r3_;
                LDSM_X4T(r0_, r1_, r2_, r3_, addr);
                b_[2*jj][0] = r0_;   b_[2*jj][1] = r1_;
                b_[2*jj+1][0] = r2_; b_[2*jj+1][1] = r3_;
            }
#pragma unroll
            for (int i = 0; i < 2; ++i)
#pragma unroll
                for (int j = 0; j < 4; ++j)
                    MMA_BF16(c[i][j][0], c[i][j][1], c[i][j][2], c[i][j][3],
                             a[i][0], a[i][1], a[i][2], a[i][3], b_[j][0], b_[j][1]);
        }
        if (ch + 3 < S2_NCH) load_stage(ch + 3);
        else CP_COMMIT();
    }

    float* O = g_midp[s];
#pragma unroll
    for (int i = 0; i < 2; ++i) {
        int row = n0 + wm * 32 + i * 16 + g;
#pragma unroll
        for (int j = 0; j < 4; ++j) {
            int col = wn * 32 + j * 8 + 2 * q;
            float2 v0 = { c[i][j][0], c[i][j][1] };
            float2 v1 = { c[i][j][2], c[i][j][3] };
            *(float2*)&O[(size_t)(b * NN + row) * OUTC + col] = v0;
            *(float2*)&O[(size_t)(b * NN + row + 8) * OUTC + col] = v1;
        }
    }
}

// ---------------- BN tail (reads both slabs directly) ----------------
__global__ void zero_stats() {
    if (threadIdx.x < OUTC) { g_sum[threadIdx.x] = 0.f; g_sumsq[threadIdx.x] = 0.f; }
}
__global__ __launch_bounds__(256) void bn_stats() {
    const int c = threadIdx.x & 63;
    const int rl = threadIdx.x >> 6;
    float s = 0.f, s2 = 0.f;
    for (int r = blockIdx.x * 4 + rl; r < ROWS; r += gridDim.x * 4) {
        size_t off = (size_t)r * OUTC + c;
        float v = g_midp[0][off] + g_midp[1][off];
        s += v; s2 += v * v;
    }
    __shared__ float sh[256], sh2[256];
    sh[threadIdx.x] = s; sh2[threadIdx.x] = s2;
    __syncthreads();
    if (rl == 0) {
        s  = sh[c] + sh[c + 64] + sh[c + 128] + sh[c + 192];
        s2 = sh2[c] + sh2[c + 64] + sh2[c + 128] + sh2[c + 192];
        atomicAdd(&g_sum[c], s); atomicAdd(&g_sumsq[c], s2);
    }
}
__global__ __launch_bounds__(256) void bn_relu_fc2(
    const float* __restrict__ gamma, const float* __restrict__ beta,
    const float* __restrict__ w2,    const float* __restrict__ b2,
    float* __restrict__ out)
{
    __shared__ float w2t[64][65];
    __shared__ float ysm[64][65];
    __shared__ float scale_s[64], shift_s[64];
    const int tid = threadIdx.x;
    const int r0 = blockIdx.x * 64;

#pragma unroll
    for (int t = 0; t < 16; ++t) {
        int idx = tid + t * 256;
        int o = idx >> 6, cc = idx & 63;
        w2t[cc][o] = w2[idx];
    }
    if (tid < OUTC) {
        const float invN = 1.0f / (float)ROWS;
        float mean = g_sum[tid] * invN;
        float var  = g_sumsq[tid] * invN - mean * mean;
        float sc   = gamma[tid] * rsqrtf(var + 1e-5f);
        scale_s[tid] = sc;
        shift_s[tid] = beta[tid] - mean * sc;
    }
    __syncthreads();

#pragma unroll
    for (int t = 0; t < 16; ++t) {
        int idx = tid + t * 256;
        int r = idx >> 6, cc = idx & 63;
        size_t off = (size_t)(r0 + r) * OUTC + cc;
        float v = g_midp[0][off] + g_midp[1][off];
        ysm[r][cc] = fmaxf(fmaf(v, scale_s[cc], shift_s[cc]), 0.f);
    }
    __syncthreads();

    const int tr = tid >> 4, tc = tid & 15;
    float acc[4][4];
#pragma unroll
    for (int i = 0; i < 4; ++i)
#pragma unroll
        for (int j = 0; j < 4; ++j) acc[i][j] = b2[tc * 4 + j];
    for (int k = 0; k < 64; ++k) {
        float w0 = w2t[k][tc * 4 + 0], w1 = w2t[k][tc * 4 + 1];
        float w2v = w2t[k][tc * 4 + 2], w3 = w2t[k][tc * 4 + 3];
#pragma unroll
        for (int i = 0; i < 4; ++i) {
            float y = ysm[tr * 4 + i][k];
            acc[i][0] = fmaf(y, w0, acc[i][0]);
            acc[i][1] = fmaf(y, w1, acc[i][1]);
            acc[i][2] = fmaf(y, w2v, acc[i][2]);
            acc[i][3] = fmaf(y, w3, acc[i][3]);
        }
    }
#pragma unroll
    for (int i = 0; i < 4; ++i)
        *(float4*)&out[(size_t)(r0 + tr * 4 + i) * OUTC + tc * 4] = *(float4*)&acc[i][0];
}

// ---------------- launch ----------------
extern "C" void kernel_launch(void* const* d_in, const int* in_sizes, int n_in,
                              void* d_out, int out_size) {
    const float* x       = (const float*)d_in[0];
    const float* support = (const float*)d_in[1];
    const float* weight  = (const float*)d_in[2];
    const float* eps     = (const float*)d_in[3];
    const float* gamma   = (const float*)d_in[4];
    const float* beta    = (const float*)d_in[5];
    const float* w2      = (const float*)d_in[6];
    const float* b2      = (const float*)d_in[7];
    float* out           = (float*)d_out;

    cudaFuncSetAttribute(stage1_mma,  cudaFuncAttributeMaxDynamicSharedMemorySize, S1_SMEM);
    cudaFuncSetAttribute(stage2a_mma, cudaFuncAttributeMaxDynamicSharedMemorySize, S2_SMEM);
    cudaFuncSetAttribute(stage2b_mma, cudaFuncAttributeMaxDynamicSharedMemorySize, S2_SMEM);

    prep_M<<<(2 * (int)AS + 255) / 256, 256>>>(support, eps);
    prep_W<<<(ZC * BD + 255) / 256, 256>>>(weight);
    split_X<<<(int)(ROWS * (size_t)BD / 4 + 255) / 256, 256>>>(x);

    stage1_mma<<<dim3(ZC / 128, ROWS / 128), 256, S1_SMEM>>>();

    stage2a_mma<<<dim3(NN / 128, BB, 2), 256, S2_SMEM>>>();
    vadd_split<<<(2 * ROWS * 32 + 255) / 256, 256>>>();
    stage2b_mma<<<dim3(NN / 128, BB, 2), 256, S2_SMEM>>>();

    zero_stats<<<1, 64>>>();
    bn_stats<<<128, 256>>>();
    bn_relu_fc2<<<ROWS / 64, 256>>>(gamma, beta, w2, b2, out);
}